// round 12
// baseline (speedup 1.0000x reference)
#include <cuda_runtime.h>
#include <cuda_bf16.h>
#include <math.h>
#include <stdint.h>

// Problem constants (fixed shapes)
#define NN 50000
#define EE 800000
#define DIN 256
#define HH 128
#define RR 8
#define HEADS 8
#define DHH 16
#define OUTC 3
#define KW_H 64     // HH/2 packed words per row
#define KW_X 128    // DIN/2 packed words per row

// ---------------- scratch (device globals; no allocation allowed) ----------
__device__ float    g_Y[(size_t)NN * RR * HH];      // [n][r*128+j]
__device__ float    g_agg[(size_t)NN * HH];
__device__ uint32_t g_xhi[(size_t)NN * KW_X], g_xlo[(size_t)NN * KW_X];
__device__ uint32_t g_hAhi[(size_t)NN * KW_H], g_hAlo[(size_t)NN * KW_H];
__device__ uint32_t g_hBhi[(size_t)NN * KW_H], g_hBlo[(size_t)NN * KW_H];
__device__ uint32_t g_w1hi[9 * KW_H * HH], g_w1lo[9 * KW_H * HH];   // W1[0..7] + root1
__device__ uint32_t g_w2hi[9 * KW_H * HH], g_w2lo[9 * KW_H * HH];   // W2[0..7] + root2
__device__ uint32_t g_wphi[KW_X * HH], g_wplo[KW_X * HH];
__device__ uint32_t g_wghi[KW_H * HH], g_wglo[KW_H * HH];
__device__ float    g_z[(size_t)NN * HH];
__device__ float    g_deg[(size_t)NN * RR];          // degree -> invdeg in place
__device__ float    g_asrc[(size_t)NN * HEADS];
__device__ float    g_atgt[(size_t)NN * HEADS];
__device__ float    g_denom[(size_t)NN * HEADS];
__device__ float    g_outun[(size_t)NN * HH];
__device__ int2     g_es[(size_t)EE];                // type-sorted (src*8+r, tgt*8+r)
__device__ int      g_tcnt[RR];                      // per-type counters / cursors

// ---------------- helpers ----------------
__device__ __forceinline__ void red4(float* p, float a, float b, float c, float d) {
    asm volatile("red.global.add.v4.f32 [%0], {%1,%2,%3,%4};"
                 :: "l"(p), "f"(a), "f"(b), "f"(c), "f"(d) : "memory");
}

// split float pair (x = k even, y = k odd) into packed bf16x2 hi + lo
__device__ __forceinline__ void split2(float x, float y, uint32_t& hp, uint32_t& lp) {
    __nv_bfloat16 xh = __float2bfloat16(x);
    __nv_bfloat16 yh = __float2bfloat16(y);
    float xr = x - __bfloat162float(xh);
    float yr = y - __bfloat162float(yh);
    __nv_bfloat16 xl = __float2bfloat16(xr);
    __nv_bfloat16 yl = __float2bfloat16(yr);
    hp = ((uint32_t)__bfloat16_as_ushort(yh) << 16) | (uint32_t)__bfloat16_as_ushort(xh);
    lp = ((uint32_t)__bfloat16_as_ushort(yl) << 16) | (uint32_t)__bfloat16_as_ushort(xl);
}

__device__ __forceinline__ void mma_bf16(float& c0, float& c1, float& c2, float& c3,
                                         uint32_t a0, uint32_t a1, uint32_t a2, uint32_t a3,
                                         uint32_t b0, uint32_t b1) {
    asm volatile("mma.sync.aligned.m16n8k16.row.col.f32.bf16.bf16.f32 "
                 "{%0,%1,%2,%3}, {%4,%5,%6,%7}, {%8,%9}, {%0,%1,%2,%3};"
                 : "+f"(c0), "+f"(c1), "+f"(c2), "+f"(c3)
                 : "r"(a0), "r"(a1), "r"(a2), "r"(a3), "r"(b0), "r"(b1));
}

// ---------------- fill / pack / split kernels ----------------
__global__ void fill_f4(float4* p, int n4, float v) {
    float4 q = make_float4(v, v, v, v);
    for (int i = blockIdx.x * blockDim.x + threadIdx.x; i < n4; i += gridDim.x * blockDim.x)
        p[i] = q;
}
__global__ void fill_i(int* p, int n, int v) {
    int i = blockIdx.x * blockDim.x + threadIdx.x;
    if (i < n) p[i] = v;
}

// pack B chunks: fp32 [2*Kw x 128] row-major -> [Kw][128] hi/lo bf16x2 (pairs along K)
__global__ void pack_b(const float* __restrict__ srcW, const float* __restrict__ srcRoot,
                       uint32_t* __restrict__ dhi, uint32_t* __restrict__ dlo, int Kw) {
    int y = blockIdx.y;
    const float* src = (srcRoot != nullptr && y == (int)gridDim.y - 1)
                       ? srcRoot : srcW + (size_t)y * Kw * 2 * HH;
    int i = blockIdx.x * blockDim.x + threadIdx.x;
    if (i >= Kw * HH) return;
    int kp = i >> 7, n = i & 127;
    float a = src[(size_t)(2 * kp) * HH + n];
    float b = src[(size_t)(2 * kp + 1) * HH + n];
    uint32_t hp, lp; split2(a, b, hp, lp);
    dhi[(size_t)y * Kw * HH + i] = hp;
    dlo[(size_t)y * Kw * HH + i] = lp;
}

// split a contiguous row-major fp32 matrix into packed hi/lo words (pairs along row)
__global__ void split_mat(const float* __restrict__ src, uint32_t* __restrict__ dhi,
                          uint32_t* __restrict__ dlo, int nwords) {
    int i = blockIdx.x * blockDim.x + threadIdx.x;
    if (i >= nwords) return;
    float2 v = ((const float2*)src)[i];
    uint32_t hp, lp; split2(v.x, v.y, hp, lp);
    dhi[i] = hp; dlo[i] = lp;
}

// ---------------- edge sort by type (counting sort) ----------------
__global__ void type_count(const int* __restrict__ et, int* __restrict__ cnt, int E) {
    __shared__ int h[RR];
    if (threadIdx.x < RR) h[threadIdx.x] = 0;
    __syncthreads();
    for (int i = blockIdx.x * blockDim.x + threadIdx.x; i < E; i += gridDim.x * blockDim.x)
        atomicAdd(&h[et[i]], 1);
    __syncthreads();
    if (threadIdx.x < RR) atomicAdd(&cnt[threadIdx.x], h[threadIdx.x]);
}
__global__ void type_scan(int* cnt) {   // single thread: counts -> start cursors
    if (threadIdx.x == 0 && blockIdx.x == 0) {
        int acc = 0;
#pragma unroll
        for (int r = 0; r < RR; r++) { int c = cnt[r]; cnt[r] = acc; acc += c; }
    }
}
__global__ void type_fill(const int* __restrict__ src, const int* __restrict__ tgt,
                          const int* __restrict__ et, int* __restrict__ cur,
                          int2* __restrict__ es, int E) {
    int e = blockIdx.x * blockDim.x + threadIdx.x;
    if (e >= E) return;
    int r = et[e];
    int slot = atomicAdd(&cur[r], 1);
    es[slot] = make_int2(src[e] * RR + r, tgt[e] * RR + r);
}

// ---------------- packed-operand bf16x3 tensor-core GEMM ----------------
// C[M,128] = A@B where A,B are pre-split hi/lo bf16x2 word arrays.
// EPI 0: f32 out Cf (ld=HH). EPI 1: packed hi/lo out + bias. EPI 2: rgcn dual
//        (blockIdx.y<8 -> Y at col-offset by*128, ld=RR*HH; by==8 -> Cagg, ld=HH).
template<int EPI>
__global__ __launch_bounds__(256, 2) void gemm_pk(
    const uint32_t* __restrict__ Ahi, const uint32_t* __restrict__ Alo,
    const uint32_t* __restrict__ Bhi_base, const uint32_t* __restrict__ Blo_base,
    const float* __restrict__ bias,
    float* __restrict__ Cf, float* __restrict__ Cagg,
    uint32_t* __restrict__ Chi, uint32_t* __restrict__ Clo,
    int M, int Kw)
{
    constexpr int LDSW = 136;
    __shared__ uint32_t As_h[8][LDSW], As_l[8][LDSW];   // [kpair][row]
    __shared__ uint32_t Bs_h[8][LDSW], Bs_l[8][LDSW];   // [kpair][col]

    const int tid = threadIdx.x;
    const int lane = tid & 31;
    const int warp = tid >> 5;
    const int warp_m = warp & 3;
    const int warp_n = warp >> 2;
    const int bm = blockIdx.x * 128;
    const int by = blockIdx.y;

    const uint32_t* Bhi = Bhi_base + (size_t)by * Kw * HH;
    const uint32_t* Blo = Blo_base + (size_t)by * Kw * HH;

    const int a_row = tid & 127;
    const int a_kq = (tid >> 7) << 2;
    const int b_kp = tid >> 5;
    const int b_n4 = (tid & 31) << 2;

    const int row_g = bm + a_row;
    const bool row_ok = (row_g < M);

    const int tig = lane & 3;
    const int gid = lane >> 2;

    float c[2][8][4];
#pragma unroll
    for (int i = 0; i < 2; i++)
#pragma unroll
        for (int j = 0; j < 8; j++)
#pragma unroll
            for (int q = 0; q < 4; q++) c[i][j][q] = 0.0f;

#pragma unroll 1
    for (int kp0 = 0; kp0 < Kw; kp0 += 8) {
        uint4 vh = make_uint4(0, 0, 0, 0), vl = make_uint4(0, 0, 0, 0);
        if (row_ok) {
            vh = *(const uint4*)(Ahi + (size_t)row_g * Kw + kp0 + a_kq);
            vl = *(const uint4*)(Alo + (size_t)row_g * Kw + kp0 + a_kq);
        }
        As_h[a_kq + 0][a_row] = vh.x; As_h[a_kq + 1][a_row] = vh.y;
        As_h[a_kq + 2][a_row] = vh.z; As_h[a_kq + 3][a_row] = vh.w;
        As_l[a_kq + 0][a_row] = vl.x; As_l[a_kq + 1][a_row] = vl.y;
        As_l[a_kq + 2][a_row] = vl.z; As_l[a_kq + 3][a_row] = vl.w;
        {
            uint4 bh = *(const uint4*)(Bhi + (size_t)(kp0 + b_kp) * HH + b_n4);
            uint4 bl = *(const uint4*)(Blo + (size_t)(kp0 + b_kp) * HH + b_n4);
            *(uint4*)&Bs_h[b_kp][b_n4] = bh;
            *(uint4*)&Bs_l[b_kp][b_n4] = bl;
        }
        __syncthreads();

        uint32_t ah[2][4], al[2][4];
#pragma unroll
        for (int mt = 0; mt < 2; mt++) {
            int r = warp_m * 32 + mt * 16 + gid;
            ah[mt][0] = As_h[tig][r];     ah[mt][1] = As_h[tig][r + 8];
            ah[mt][2] = As_h[tig + 4][r]; ah[mt][3] = As_h[tig + 4][r + 8];
            al[mt][0] = As_l[tig][r];     al[mt][1] = As_l[tig][r + 8];
            al[mt][2] = As_l[tig + 4][r]; al[mt][3] = As_l[tig + 4][r + 8];
        }
#pragma unroll
        for (int half = 0; half < 2; half++) {
            uint32_t bh[4][2], bl[4][2];
#pragma unroll
            for (int n4 = 0; n4 < 4; n4++) {
                int cc = warp_n * 64 + (half * 4 + n4) * 8 + gid;
                bh[n4][0] = Bs_h[tig][cc]; bh[n4][1] = Bs_h[tig + 4][cc];
                bl[n4][0] = Bs_l[tig][cc]; bl[n4][1] = Bs_l[tig + 4][cc];
            }
#pragma unroll
            for (int mt = 0; mt < 2; mt++)
#pragma unroll
                for (int n4 = 0; n4 < 4; n4++) {
                    int nt = half * 4 + n4;
                    mma_bf16(c[mt][nt][0], c[mt][nt][1], c[mt][nt][2], c[mt][nt][3],
                             ah[mt][0], ah[mt][1], ah[mt][2], ah[mt][3],
                             bh[n4][0], bh[n4][1]);
                    mma_bf16(c[mt][nt][0], c[mt][nt][1], c[mt][nt][2], c[mt][nt][3],
                             ah[mt][0], ah[mt][1], ah[mt][2], ah[mt][3],
                             bl[n4][0], bl[n4][1]);
                    mma_bf16(c[mt][nt][0], c[mt][nt][1], c[mt][nt][2], c[mt][nt][3],
                             al[mt][0], al[mt][1], al[mt][2], al[mt][3],
                             bh[n4][0], bh[n4][1]);
                }
        }
        __syncthreads();
    }

    const int er0 = bm + warp_m * 32 + gid;
    const int ec0 = warp_n * 64 + (tig << 1);
#pragma unroll
    for (int mt = 0; mt < 2; mt++) {
#pragma unroll
        for (int half = 0; half < 2; half++) {
            int row = er0 + mt * 16 + half * 8;
            if (row >= M) continue;
#pragma unroll
            for (int nt = 0; nt < 8; nt++) {
                int col = ec0 + nt * 8;
                float v0 = c[mt][nt][half * 2 + 0];
                float v1 = c[mt][nt][half * 2 + 1];
                if (EPI == 1 && bias) { v0 += bias[col]; v1 += bias[col + 1]; }
                if (EPI == 0) {
                    *(float2*)(Cf + (size_t)row * HH + col) = make_float2(v0, v1);
                } else if (EPI == 1) {
                    uint32_t hp, lp; split2(v0, v1, hp, lp);
                    Chi[(size_t)row * KW_H + (col >> 1)] = hp;
                    Clo[(size_t)row * KW_H + (col >> 1)] = lp;
                } else {
                    if (by < 8)
                        *(float2*)(Cf + (size_t)row * (RR * HH) + by * HH + col) = make_float2(v0, v1);
                    else
                        *(float2*)(Cagg + (size_t)row * HH + col) = make_float2(v0, v1);
                }
            }
        }
    }
}

// ---------------- degree + scatter + layer-finalize ----------------
__global__ void deg_count(const int* __restrict__ tgt, const int* __restrict__ et,
                          float* __restrict__ deg, int E) {
    int e = blockIdx.x * blockDim.x + threadIdx.x;
    if (e >= E) return;
    atomicAdd(deg + (size_t)tgt[e] * RR + et[e], 1.0f);
}

__global__ void make_invdeg(float* deg, int n) {
    int i = blockIdx.x * blockDim.x + threadIdx.x;
    if (i < n) deg[i] = 1.0f / fmaxf(deg[i], 1.0f);
}

// warp per edge, type-sorted: agg[tgt] += Y[src, r] * invdeg[tgt, r]
__global__ void scatter_edges(const int2* __restrict__ es, const float* __restrict__ Y,
                              const float* __restrict__ invdeg, float* __restrict__ agg, int E)
{
    int w = (blockIdx.x * blockDim.x + threadIdx.x) >> 5;
    int lane = threadIdx.x & 31;
    if (w >= E) return;
    int2 p = es[w];                      // (src*8+r, tgt*8+r)
    float iv = invdeg[p.y];
    float4 v = ((const float4*)(Y + (size_t)p.x * HH))[lane];
    red4(agg + (size_t)(p.y >> 3) * HH + lane * 4, v.x * iv, v.y * iv, v.z * iv, v.w * iv);
}

// h_next = relu(agg + b) -> packed hi/lo
__global__ void layer_fin(const float* __restrict__ agg, const float* __restrict__ b,
                          uint32_t* __restrict__ dhi, uint32_t* __restrict__ dlo, int nwords)
{
    int i = blockIdx.x * blockDim.x + threadIdx.x;
    if (i >= nwords) return;
    int col2 = (i & (KW_H - 1)) << 1;
    float2 v = ((const float2*)agg)[i];
    float v0 = fmaxf(v.x + b[col2], 0.f);
    float v1 = fmaxf(v.y + b[col2 + 1], 0.f);
    uint32_t hp, lp; split2(v0, v1, hp, lp);
    dhi[i] = hp; dlo[i] = lp;
}

// ---------------- GAT ----------------
__global__ void att_node(const float* __restrict__ z, const float* __restrict__ att,
                         float* __restrict__ asrc, float* __restrict__ atgt, int n)
{
    int i = blockIdx.x * blockDim.x + threadIdx.x;
    if (i >= n * HEADS) return;
    int node = i >> 3, hd = i & 7;
    const float* zp = z + (size_t)node * HH + hd * DHH;
    const float* al = att + hd * (2 * DHH);
    float sa = 0.f, sb = 0.f;
#pragma unroll
    for (int d = 0; d < DHH; d++) {
        float zv = zp[d];
        sa += zv * al[d];
        sb += zv * al[DHH + d];
    }
    asrc[i] = sa;
    atgt[i] = sb;
}

// fused single-pass GAT: no max-shift (softmax shift-invariant; alpha bounded small).
// warp per edge: ex = exp(leaky(asrc[s]+atgt[t])); denom += ex; outun[t] += z[s]*ex
__global__ void gat_fused(const int* __restrict__ src, const int* __restrict__ tgt,
                          const float* __restrict__ asrc, const float* __restrict__ atgt,
                          const float* __restrict__ z, float* __restrict__ denom,
                          float* __restrict__ outun, int E)
{
    int w = (blockIdx.x * blockDim.x + threadIdx.x) >> 5;
    int lane = threadIdx.x & 31;
    if (w >= E) return;
    int s = src[w], t = tgt[w];
    int head = lane >> 2;
    float a = asrc[(size_t)s * HEADS + head] + atgt[(size_t)t * HEADS + head];
    a = a > 0.f ? a : 0.2f * a;
    float ex = __expf(a);
    if ((lane & 3) == 0) atomicAdd(denom + (size_t)t * HEADS + head, ex);
    float4 zv = ((const float4*)(z + (size_t)s * HH))[lane];
    red4(outun + (size_t)t * HH + lane * 4, zv.x * ex, zv.y * ex, zv.z * ex, zv.w * ex);
}

// finalize: gat-normalize + bg, then 128x3 projection, log_softmax. Warp per node.
__global__ void finalize(const float* __restrict__ outun, const float* __restrict__ denom,
                         const float* __restrict__ bg, const float* __restrict__ Wf,
                         const float* __restrict__ bf, float* __restrict__ out, int n)
{
    int w = (blockIdx.x * blockDim.x + threadIdx.x) >> 5;
    int lane = threadIdx.x & 31;
    if (w >= n) return;
    float4 g = ((const float4*)(outun + (size_t)w * HH))[lane];
    int head = lane >> 2;
    float dn = denom[(size_t)w * HEADS + head];
    float inv = 1.0f / fmaxf(dn, 1e-16f);
    float4 bgv = ((const float4*)bg)[lane];
    float gv[4] = { g.x * inv + bgv.x, g.y * inv + bgv.y,
                    g.z * inv + bgv.z, g.w * inv + bgv.w };
    float a0 = 0.f, a1 = 0.f, a2 = 0.f;
    int j0 = lane * 4;
#pragma unroll
    for (int c = 0; c < 4; c++) {
        int j = j0 + c;
        a0 += gv[c] * Wf[j * OUTC + 0];
        a1 += gv[c] * Wf[j * OUTC + 1];
        a2 += gv[c] * Wf[j * OUTC + 2];
    }
#pragma unroll
    for (int off = 16; off > 0; off >>= 1) {
        a0 += __shfl_xor_sync(0xFFFFFFFFu, a0, off);
        a1 += __shfl_xor_sync(0xFFFFFFFFu, a1, off);
        a2 += __shfl_xor_sync(0xFFFFFFFFu, a2, off);
    }
    if (lane == 0) {
        float l0 = a0 + bf[0], l1 = a1 + bf[1], l2 = a2 + bf[2];
        float m = fmaxf(l0, fmaxf(l1, l2));
        float lse = m + logf(expf(l0 - m) + expf(l1 - m) + expf(l2 - m));
        out[(size_t)w * OUTC + 0] = l0 - lse;
        out[(size_t)w * OUTC + 1] = l1 - lse;
        out[(size_t)w * OUTC + 2] = l2 - lse;
    }
}

// ---------------- launch ----------------
extern "C" void kernel_launch(void* const* d_in, const int* in_sizes, int n_in,
                              void* d_out, int out_size)
{
    const float* x     = (const float*)d_in[0];
    const int*   ei    = (const int*)d_in[1];
    const int*   etype = (const int*)d_in[2];
    const float* Wp    = (const float*)d_in[3];
    const float* bp    = (const float*)d_in[4];
    const float* W1    = (const float*)d_in[5];
    const float* root1 = (const float*)d_in[6];
    const float* b1    = (const float*)d_in[7];
    const float* W2    = (const float*)d_in[8];
    const float* root2 = (const float*)d_in[9];
    const float* b2    = (const float*)d_in[10];
    const float* Wg    = (const float*)d_in[11];
    const float* att   = (const float*)d_in[12];
    const float* bg    = (const float*)d_in[13];
    const float* Wf    = (const float*)d_in[14];
    const float* bf    = (const float*)d_in[15];
    float* out = (float*)d_out;

    const int* src = ei;
    const int* tgt = ei + EE;

    float *Y, *agg, *z, *deg, *asrc, *atgt, *denom, *outun;
    uint32_t *xhi, *xlo, *hAhi, *hAlo, *hBhi, *hBlo;
    uint32_t *w1hi, *w1lo, *w2hi, *w2lo, *wphi, *wplo, *wghi, *wglo;
    int2* es; int* tcnt;
    cudaGetSymbolAddress((void**)&Y, g_Y);
    cudaGetSymbolAddress((void**)&agg, g_agg);
    cudaGetSymbolAddress((void**)&z, g_z);
    cudaGetSymbolAddress((void**)&deg, g_deg);
    cudaGetSymbolAddress((void**)&asrc, g_asrc);
    cudaGetSymbolAddress((void**)&atgt, g_atgt);
    cudaGetSymbolAddress((void**)&denom, g_denom);
    cudaGetSymbolAddress((void**)&outun, g_outun);
    cudaGetSymbolAddress((void**)&xhi, g_xhi);
    cudaGetSymbolAddress((void**)&xlo, g_xlo);
    cudaGetSymbolAddress((void**)&hAhi, g_hAhi);
    cudaGetSymbolAddress((void**)&hAlo, g_hAlo);
    cudaGetSymbolAddress((void**)&hBhi, g_hBhi);
    cudaGetSymbolAddress((void**)&hBlo, g_hBlo);
    cudaGetSymbolAddress((void**)&w1hi, g_w1hi);
    cudaGetSymbolAddress((void**)&w1lo, g_w1lo);
    cudaGetSymbolAddress((void**)&w2hi, g_w2hi);
    cudaGetSymbolAddress((void**)&w2lo, g_w2lo);
    cudaGetSymbolAddress((void**)&wphi, g_wphi);
    cudaGetSymbolAddress((void**)&wplo, g_wplo);
    cudaGetSymbolAddress((void**)&wghi, g_wghi);
    cudaGetSymbolAddress((void**)&wglo, g_wglo);
    cudaGetSymbolAddress((void**)&es, g_es);
    cudaGetSymbolAddress((void**)&tcnt, g_tcnt);

    const int gemmGrid = (NN + 127) / 128;   // 391
    const int scatGrid = (EE + 7) / 8;

    // ---- one-time packs / splits / degrees / edge sort ----
    {
        dim3 g1((KW_H * HH + 255) / 256, 9);
        pack_b<<<g1, 256>>>(W1, root1, w1hi, w1lo, KW_H);
        pack_b<<<g1, 256>>>(W2, root2, w2hi, w2lo, KW_H);
        dim3 g2((KW_X * HH + 255) / 256, 1);
        pack_b<<<g2, 256>>>(Wp, nullptr, wphi, wplo, KW_X);
        dim3 g3((KW_H * HH + 255) / 256, 1);
        pack_b<<<g3, 256>>>(Wg, nullptr, wghi, wglo, KW_H);
    }
    split_mat<<<(NN * KW_X + 255) / 256, 256>>>(x, xhi, xlo, NN * KW_X);
    fill_f4<<<64, 256>>>((float4*)deg, NN * RR / 4, 0.f);
    deg_count<<<(EE + 255) / 256, 256>>>(tgt, etype, deg, EE);
    make_invdeg<<<(NN * RR + 255) / 256, 256>>>(deg, NN * RR);
    fill_i<<<1, 32>>>(tcnt, RR, 0);
    type_count<<<512, 256>>>(etype, tcnt, EE);
    type_scan<<<1, 1>>>(tcnt);
    type_fill<<<(EE + 255) / 256, 256>>>(src, tgt, etype, tcnt, es, EE);

    // ---- projection: hA = pack(x @ Wp + bp)
    gemm_pk<1><<<dim3(gemmGrid, 1), 256>>>(xhi, xlo, wphi, wplo, bp,
                                           nullptr, nullptr, hAhi, hAlo, NN, KW_X);

    // ---- RGCN layer 1 ----
    gemm_pk<2><<<dim3(gemmGrid, 9), 256>>>(hAhi, hAlo, w1hi, w1lo, nullptr,
                                           Y, agg, nullptr, nullptr, NN, KW_H);
    scatter_edges<<<scatGrid, 256>>>(es, Y, deg, agg, EE);
    layer_fin<<<(NN * KW_H + 255) / 256, 256>>>(agg, b1, hBhi, hBlo, NN * KW_H);

    // ---- RGCN layer 2 ----
    gemm_pk<2><<<dim3(gemmGrid, 9), 256>>>(hBhi, hBlo, w2hi, w2lo, nullptr,
                                           Y, agg, nullptr, nullptr, NN, KW_H);
    scatter_edges<<<scatGrid, 256>>>(es, Y, deg, agg, EE);
    layer_fin<<<(NN * KW_H + 255) / 256, 256>>>(agg, b2, hAhi, hAlo, NN * KW_H);

    // ---- GAT ----
    gemm_pk<0><<<dim3(gemmGrid, 1), 256>>>(hAhi, hAlo, wghi, wglo, nullptr,
                                           z, nullptr, nullptr, nullptr, NN, KW_H);
    att_node<<<(NN * HEADS + 255) / 256, 256>>>(z, att, asrc, atgt, NN);
    fill_f4<<<64, 256>>>((float4*)denom, NN * HEADS / 4, 0.f);
    fill_f4<<<512, 256>>>((float4*)outun, NN * HH / 4, 0.f);
    gat_fused<<<scatGrid, 256>>>(src, tgt, asrc, atgt, z, denom, outun, EE);

    // ---- finalize
    finalize<<<(NN + 7) / 8, 256>>>(outun, denom, bg, Wf, bf, out, NN);
}

// round 13
// speedup vs baseline: 1.1011x; 1.1011x over previous
#include <cuda_runtime.h>
#include <cuda_bf16.h>
#include <math.h>
#include <stdint.h>

// Problem constants (fixed shapes)
#define NN 50000
#define EE 800000
#define DIN 256
#define HH 128
#define RR 8
#define HEADS 8
#define DHH 16
#define OUTC 3
#define KW_H 64     // HH/2 packed words per row
#define KW_X 128    // DIN/2 packed words per row

// ---------------- scratch (device globals; no allocation allowed) ----------
__device__ float    g_Y[(size_t)NN * RR * HH];      // [n][r*128+j]
__device__ float    g_agg[(size_t)NN * HH];
__device__ uint32_t g_xhi[(size_t)NN * KW_X], g_xlo[(size_t)NN * KW_X];
__device__ uint32_t g_hAhi[(size_t)NN * KW_H], g_hAlo[(size_t)NN * KW_H];
__device__ uint32_t g_hBhi[(size_t)NN * KW_H], g_hBlo[(size_t)NN * KW_H];
__device__ uint32_t g_w1hi[9 * KW_H * HH], g_w1lo[9 * KW_H * HH];   // W1[0..7] + root1
__device__ uint32_t g_w2hi[9 * KW_H * HH], g_w2lo[9 * KW_H * HH];   // W2[0..7] + root2
__device__ uint32_t g_wphi[KW_X * HH], g_wplo[KW_X * HH];
__device__ uint32_t g_wghi[KW_H * HH], g_wglo[KW_H * HH];
__device__ float    g_z[(size_t)NN * HH];
__device__ float    g_deg[(size_t)NN * RR];          // degree -> invdeg in place
__device__ float    g_asrc[(size_t)NN * HEADS];
__device__ float    g_atgt[(size_t)NN * HEADS];
__device__ float    g_denom[(size_t)NN * HEADS];
__device__ float    g_outun[(size_t)NN * HH];

// ---------------- helpers ----------------
__device__ __forceinline__ void red4(float* p, float a, float b, float c, float d) {
    asm volatile("red.global.add.v4.f32 [%0], {%1,%2,%3,%4};"
                 :: "l"(p), "f"(a), "f"(b), "f"(c), "f"(d) : "memory");
}

// split float pair (x = k even, y = k odd) into packed bf16x2 hi + lo
__device__ __forceinline__ void split2(float x, float y, uint32_t& hp, uint32_t& lp) {
    __nv_bfloat16 xh = __float2bfloat16(x);
    __nv_bfloat16 yh = __float2bfloat16(y);
    float xr = x - __bfloat162float(xh);
    float yr = y - __bfloat162float(yh);
    __nv_bfloat16 xl = __float2bfloat16(xr);
    __nv_bfloat16 yl = __float2bfloat16(yr);
    hp = ((uint32_t)__bfloat16_as_ushort(yh) << 16) | (uint32_t)__bfloat16_as_ushort(xh);
    lp = ((uint32_t)__bfloat16_as_ushort(yl) << 16) | (uint32_t)__bfloat16_as_ushort(xl);
}

__device__ __forceinline__ void mma_bf16(float& c0, float& c1, float& c2, float& c3,
                                         uint32_t a0, uint32_t a1, uint32_t a2, uint32_t a3,
                                         uint32_t b0, uint32_t b1) {
    asm volatile("mma.sync.aligned.m16n8k16.row.col.f32.bf16.bf16.f32 "
                 "{%0,%1,%2,%3}, {%4,%5,%6,%7}, {%8,%9}, {%0,%1,%2,%3};"
                 : "+f"(c0), "+f"(c1), "+f"(c2), "+f"(c3)
                 : "r"(a0), "r"(a1), "r"(a2), "r"(a3), "r"(b0), "r"(b1));
}

// ---------------- fill / pack / split kernels ----------------
__global__ void fill_f4(float4* p, int n4, float v) {
    float4 q = make_float4(v, v, v, v);
    for (int i = blockIdx.x * blockDim.x + threadIdx.x; i < n4; i += gridDim.x * blockDim.x)
        p[i] = q;
}

// pack B chunks: fp32 [2*Kw x 128] row-major -> [Kw][128] hi/lo bf16x2 (pairs along K)
__global__ void pack_b(const float* __restrict__ srcW, const float* __restrict__ srcRoot,
                       uint32_t* __restrict__ dhi, uint32_t* __restrict__ dlo, int Kw) {
    int y = blockIdx.y;
    const float* src = (srcRoot != nullptr && y == (int)gridDim.y - 1)
                       ? srcRoot : srcW + (size_t)y * Kw * 2 * HH;
    int i = blockIdx.x * blockDim.x + threadIdx.x;
    if (i >= Kw * HH) return;
    int kp = i >> 7, n = i & 127;
    float a = src[(size_t)(2 * kp) * HH + n];
    float b = src[(size_t)(2 * kp + 1) * HH + n];
    uint32_t hp, lp; split2(a, b, hp, lp);
    dhi[(size_t)y * Kw * HH + i] = hp;
    dlo[(size_t)y * Kw * HH + i] = lp;
}

// split a contiguous row-major fp32 matrix into packed hi/lo words (pairs along row)
__global__ void split_mat(const float* __restrict__ src, uint32_t* __restrict__ dhi,
                          uint32_t* __restrict__ dlo, int nwords) {
    int i = blockIdx.x * blockDim.x + threadIdx.x;
    if (i >= nwords) return;
    float2 v = ((const float2*)src)[i];
    uint32_t hp, lp; split2(v.x, v.y, hp, lp);
    dhi[i] = hp; dlo[i] = lp;
}

// ---------------- packed-operand bf16x3 tensor-core GEMM ----------------
// C[M,128] = A@B where A,B are pre-split hi/lo bf16x2 word arrays.
// EPI 0: f32 out Cf (ld=HH). EPI 1: packed hi/lo out + bias. EPI 2: rgcn dual
//        (blockIdx.y<8 -> Y at col-offset by*128, ld=RR*HH; by==8 -> Cagg, ld=HH).
template<int EPI>
__global__ __launch_bounds__(256, 2) void gemm_pk(
    const uint32_t* __restrict__ Ahi, const uint32_t* __restrict__ Alo,
    const uint32_t* __restrict__ Bhi_base, const uint32_t* __restrict__ Blo_base,
    const float* __restrict__ bias,
    float* __restrict__ Cf, float* __restrict__ Cagg,
    uint32_t* __restrict__ Chi, uint32_t* __restrict__ Clo,
    int M, int Kw)
{
    constexpr int LDSW = 136;
    __shared__ uint32_t As_h[8][LDSW], As_l[8][LDSW];   // [kpair][row]
    __shared__ uint32_t Bs_h[8][LDSW], Bs_l[8][LDSW];   // [kpair][col]

    const int tid = threadIdx.x;
    const int lane = tid & 31;
    const int warp = tid >> 5;
    const int warp_m = warp & 3;
    const int warp_n = warp >> 2;
    const int bm = blockIdx.x * 128;
    const int by = blockIdx.y;

    const uint32_t* Bhi = Bhi_base + (size_t)by * Kw * HH;
    const uint32_t* Blo = Blo_base + (size_t)by * Kw * HH;

    const int a_row = tid & 127;
    const int a_kq = (tid >> 7) << 2;
    const int b_kp = tid >> 5;
    const int b_n4 = (tid & 31) << 2;

    const int row_g = bm + a_row;
    const bool row_ok = (row_g < M);

    const int tig = lane & 3;
    const int gid = lane >> 2;

    float c[2][8][4];
#pragma unroll
    for (int i = 0; i < 2; i++)
#pragma unroll
        for (int j = 0; j < 8; j++)
#pragma unroll
            for (int q = 0; q < 4; q++) c[i][j][q] = 0.0f;

#pragma unroll 1
    for (int kp0 = 0; kp0 < Kw; kp0 += 8) {
        uint4 vh = make_uint4(0, 0, 0, 0), vl = make_uint4(0, 0, 0, 0);
        if (row_ok) {
            vh = *(const uint4*)(Ahi + (size_t)row_g * Kw + kp0 + a_kq);
            vl = *(const uint4*)(Alo + (size_t)row_g * Kw + kp0 + a_kq);
        }
        As_h[a_kq + 0][a_row] = vh.x; As_h[a_kq + 1][a_row] = vh.y;
        As_h[a_kq + 2][a_row] = vh.z; As_h[a_kq + 3][a_row] = vh.w;
        As_l[a_kq + 0][a_row] = vl.x; As_l[a_kq + 1][a_row] = vl.y;
        As_l[a_kq + 2][a_row] = vl.z; As_l[a_kq + 3][a_row] = vl.w;
        {
            uint4 bh = *(const uint4*)(Bhi + (size_t)(kp0 + b_kp) * HH + b_n4);
            uint4 bl = *(const uint4*)(Blo + (size_t)(kp0 + b_kp) * HH + b_n4);
            *(uint4*)&Bs_h[b_kp][b_n4] = bh;
            *(uint4*)&Bs_l[b_kp][b_n4] = bl;
        }
        __syncthreads();

        uint32_t ah[2][4], al[2][4];
#pragma unroll
        for (int mt = 0; mt < 2; mt++) {
            int r = warp_m * 32 + mt * 16 + gid;
            ah[mt][0] = As_h[tig][r];     ah[mt][1] = As_h[tig][r + 8];
            ah[mt][2] = As_h[tig + 4][r]; ah[mt][3] = As_h[tig + 4][r + 8];
            al[mt][0] = As_l[tig][r];     al[mt][1] = As_l[tig][r + 8];
            al[mt][2] = As_l[tig + 4][r]; al[mt][3] = As_l[tig + 4][r + 8];
        }
#pragma unroll
        for (int half = 0; half < 2; half++) {
            uint32_t bh[4][2], bl[4][2];
#pragma unroll
            for (int n4 = 0; n4 < 4; n4++) {
                int cc = warp_n * 64 + (half * 4 + n4) * 8 + gid;
                bh[n4][0] = Bs_h[tig][cc]; bh[n4][1] = Bs_h[tig + 4][cc];
                bl[n4][0] = Bs_l[tig][cc]; bl[n4][1] = Bs_l[tig + 4][cc];
            }
#pragma unroll
            for (int mt = 0; mt < 2; mt++)
#pragma unroll
                for (int n4 = 0; n4 < 4; n4++) {
                    int nt = half * 4 + n4;
                    mma_bf16(c[mt][nt][0], c[mt][nt][1], c[mt][nt][2], c[mt][nt][3],
                             ah[mt][0], ah[mt][1], ah[mt][2], ah[mt][3],
                             bh[n4][0], bh[n4][1]);
                    mma_bf16(c[mt][nt][0], c[mt][nt][1], c[mt][nt][2], c[mt][nt][3],
                             ah[mt][0], ah[mt][1], ah[mt][2], ah[mt][3],
                             bl[n4][0], bl[n4][1]);
                    mma_bf16(c[mt][nt][0], c[mt][nt][1], c[mt][nt][2], c[mt][nt][3],
                             al[mt][0], al[mt][1], al[mt][2], al[mt][3],
                             bh[n4][0], bh[n4][1]);
                }
        }
        __syncthreads();
    }

    const int er0 = bm + warp_m * 32 + gid;
    const int ec0 = warp_n * 64 + (tig << 1);
#pragma unroll
    for (int mt = 0; mt < 2; mt++) {
#pragma unroll
        for (int half = 0; half < 2; half++) {
            int row = er0 + mt * 16 + half * 8;
            if (row >= M) continue;
#pragma unroll
            for (int nt = 0; nt < 8; nt++) {
                int col = ec0 + nt * 8;
                float v0 = c[mt][nt][half * 2 + 0];
                float v1 = c[mt][nt][half * 2 + 1];
                if (EPI == 1 && bias) { v0 += bias[col]; v1 += bias[col + 1]; }
                if (EPI == 0) {
                    *(float2*)(Cf + (size_t)row * HH + col) = make_float2(v0, v1);
                } else if (EPI == 1) {
                    uint32_t hp, lp; split2(v0, v1, hp, lp);
                    Chi[(size_t)row * KW_H + (col >> 1)] = hp;
                    Clo[(size_t)row * KW_H + (col >> 1)] = lp;
                } else {
                    if (by < 8)
                        *(float2*)(Cf + (size_t)row * (RR * HH) + by * HH + col) = make_float2(v0, v1);
                    else
                        *(float2*)(Cagg + (size_t)row * HH + col) = make_float2(v0, v1);
                }
            }
        }
    }
}

// ---------------- degree + scatter + layer-finalize ----------------
__global__ void deg_count(const int* __restrict__ tgt, const int* __restrict__ et,
                          float* __restrict__ deg, int E) {
    int e = blockIdx.x * blockDim.x + threadIdx.x;
    if (e >= E) return;
    atomicAdd(deg + (size_t)tgt[e] * RR + et[e], 1.0f);
}

__global__ void make_invdeg(float* deg, int n) {
    int i = blockIdx.x * blockDim.x + threadIdx.x;
    if (i < n) deg[i] = 1.0f / fmaxf(deg[i], 1.0f);
}

// warp per edge: agg[tgt] += Y[src, etype] * invdeg[tgt, etype]
__global__ void scatter_edges(const int* __restrict__ src, const int* __restrict__ tgt,
                              const int* __restrict__ et, const float* __restrict__ Y,
                              const float* __restrict__ invdeg, float* __restrict__ agg, int E)
{
    int w = (blockIdx.x * blockDim.x + threadIdx.x) >> 5;
    int lane = threadIdx.x & 31;
    if (w >= E) return;
    int s = src[w], t = tgt[w], r = et[w];
    float iv = invdeg[(size_t)t * RR + r];
    float4 v = ((const float4*)(Y + (size_t)s * (RR * HH) + r * HH))[lane];
    red4(agg + (size_t)t * HH + lane * 4, v.x * iv, v.y * iv, v.z * iv, v.w * iv);
}

// h_next = relu(agg + b) -> packed hi/lo
__global__ void layer_fin(const float* __restrict__ agg, const float* __restrict__ b,
                          uint32_t* __restrict__ dhi, uint32_t* __restrict__ dlo, int nwords)
{
    int i = blockIdx.x * blockDim.x + threadIdx.x;
    if (i >= nwords) return;
    int col2 = (i & (KW_H - 1)) << 1;
    float2 v = ((const float2*)agg)[i];
    float v0 = fmaxf(v.x + b[col2], 0.f);
    float v1 = fmaxf(v.y + b[col2 + 1], 0.f);
    uint32_t hp, lp; split2(v0, v1, hp, lp);
    dhi[i] = hp; dlo[i] = lp;
}

// ---------------- GAT ----------------
__global__ void att_node(const float* __restrict__ z, const float* __restrict__ att,
                         float* __restrict__ asrc, float* __restrict__ atgt, int n)
{
    int i = blockIdx.x * blockDim.x + threadIdx.x;
    if (i >= n * HEADS) return;
    int node = i >> 3, hd = i & 7;
    const float* zp = z + (size_t)node * HH + hd * DHH;
    const float* al = att + hd * (2 * DHH);
    float sa = 0.f, sb = 0.f;
#pragma unroll
    for (int d = 0; d < DHH; d++) {
        float zv = zp[d];
        sa += zv * al[d];
        sb += zv * al[DHH + d];
    }
    asrc[i] = sa;
    atgt[i] = sb;
}

// fused single-pass GAT: no max-shift (softmax shift-invariant; alpha bounded small).
// warp per edge: ex = exp(leaky(asrc[s]+atgt[t])); denom += ex; outun[t] += z[s]*ex
__global__ void gat_fused(const int* __restrict__ src, const int* __restrict__ tgt,
                          const float* __restrict__ asrc, const float* __restrict__ atgt,
                          const float* __restrict__ z, float* __restrict__ denom,
                          float* __restrict__ outun, int E)
{
    int w = (blockIdx.x * blockDim.x + threadIdx.x) >> 5;
    int lane = threadIdx.x & 31;
    if (w >= E) return;
    int s = src[w], t = tgt[w];
    int head = lane >> 2;
    float a = asrc[(size_t)s * HEADS + head] + atgt[(size_t)t * HEADS + head];
    a = a > 0.f ? a : 0.2f * a;
    float ex = __expf(a);
    if ((lane & 3) == 0) atomicAdd(denom + (size_t)t * HEADS + head, ex);
    float4 zv = ((const float4*)(z + (size_t)s * HH))[lane];
    red4(outun + (size_t)t * HH + lane * 4, zv.x * ex, zv.y * ex, zv.z * ex, zv.w * ex);
}

// finalize: gat-normalize + bg, then 128x3 projection, log_softmax. Warp per node.
__global__ void finalize(const float* __restrict__ outun, const float* __restrict__ denom,
                         const float* __restrict__ bg, const float* __restrict__ Wf,
                         const float* __restrict__ bf, float* __restrict__ out, int n)
{
    int w = (blockIdx.x * blockDim.x + threadIdx.x) >> 5;
    int lane = threadIdx.x & 31;
    if (w >= n) return;
    float4 g = ((const float4*)(outun + (size_t)w * HH))[lane];
    int head = lane >> 2;
    float dn = denom[(size_t)w * HEADS + head];
    float inv = 1.0f / fmaxf(dn, 1e-16f);
    float4 bgv = ((const float4*)bg)[lane];
    float gv[4] = { g.x * inv + bgv.x, g.y * inv + bgv.y,
                    g.z * inv + bgv.z, g.w * inv + bgv.w };
    float a0 = 0.f, a1 = 0.f, a2 = 0.f;
    int j0 = lane * 4;
#pragma unroll
    for (int c = 0; c < 4; c++) {
        int j = j0 + c;
        a0 += gv[c] * Wf[j * OUTC + 0];
        a1 += gv[c] * Wf[j * OUTC + 1];
        a2 += gv[c] * Wf[j * OUTC + 2];
    }
#pragma unroll
    for (int off = 16; off > 0; off >>= 1) {
        a0 += __shfl_xor_sync(0xFFFFFFFFu, a0, off);
        a1 += __shfl_xor_sync(0xFFFFFFFFu, a1, off);
        a2 += __shfl_xor_sync(0xFFFFFFFFu, a2, off);
    }
    if (lane == 0) {
        float l0 = a0 + bf[0], l1 = a1 + bf[1], l2 = a2 + bf[2];
        float m = fmaxf(l0, fmaxf(l1, l2));
        float lse = m + logf(expf(l0 - m) + expf(l1 - m) + expf(l2 - m));
        out[(size_t)w * OUTC + 0] = l0 - lse;
        out[(size_t)w * OUTC + 1] = l1 - lse;
        out[(size_t)w * OUTC + 2] = l2 - lse;
    }
}

// ---------------- launch ----------------
extern "C" void kernel_launch(void* const* d_in, const int* in_sizes, int n_in,
                              void* d_out, int out_size)
{
    const float* x     = (const float*)d_in[0];
    const int*   ei    = (const int*)d_in[1];
    const int*   etype = (const int*)d_in[2];
    const float* Wp    = (const float*)d_in[3];
    const float* bp    = (const float*)d_in[4];
    const float* W1    = (const float*)d_in[5];
    const float* root1 = (const float*)d_in[6];
    const float* b1    = (const float*)d_in[7];
    const float* W2    = (const float*)d_in[8];
    const float* root2 = (const float*)d_in[9];
    const float* b2    = (const float*)d_in[10];
    const float* Wg    = (const float*)d_in[11];
    const float* att   = (const float*)d_in[12];
    const float* bg    = (const float*)d_in[13];
    const float* Wf    = (const float*)d_in[14];
    const float* bf    = (const float*)d_in[15];
    float* out = (float*)d_out;

    const int* src = ei;
    const int* tgt = ei + EE;

    float *Y, *agg, *z, *deg, *asrc, *atgt, *denom, *outun;
    uint32_t *xhi, *xlo, *hAhi, *hAlo, *hBhi, *hBlo;
    uint32_t *w1hi, *w1lo, *w2hi, *w2lo, *wphi, *wplo, *wghi, *wglo;
    cudaGetSymbolAddress((void**)&Y, g_Y);
    cudaGetSymbolAddress((void**)&agg, g_agg);
    cudaGetSymbolAddress((void**)&z, g_z);
    cudaGetSymbolAddress((void**)&deg, g_deg);
    cudaGetSymbolAddress((void**)&asrc, g_asrc);
    cudaGetSymbolAddress((void**)&atgt, g_atgt);
    cudaGetSymbolAddress((void**)&denom, g_denom);
    cudaGetSymbolAddress((void**)&outun, g_outun);
    cudaGetSymbolAddress((void**)&xhi, g_xhi);
    cudaGetSymbolAddress((void**)&xlo, g_xlo);
    cudaGetSymbolAddress((void**)&hAhi, g_hAhi);
    cudaGetSymbolAddress((void**)&hAlo, g_hAlo);
    cudaGetSymbolAddress((void**)&hBhi, g_hBhi);
    cudaGetSymbolAddress((void**)&hBlo, g_hBlo);
    cudaGetSymbolAddress((void**)&w1hi, g_w1hi);
    cudaGetSymbolAddress((void**)&w1lo, g_w1lo);
    cudaGetSymbolAddress((void**)&w2hi, g_w2hi);
    cudaGetSymbolAddress((void**)&w2lo, g_w2lo);
    cudaGetSymbolAddress((void**)&wphi, g_wphi);
    cudaGetSymbolAddress((void**)&wplo, g_wplo);
    cudaGetSymbolAddress((void**)&wghi, g_wghi);
    cudaGetSymbolAddress((void**)&wglo, g_wglo);

    const int gemmGrid = (NN + 127) / 128;   // 391
    const int scatGrid = (EE + 7) / 8;

    // ---- one-time packs / splits / degrees ----
    {
        dim3 g1((KW_H * HH + 255) / 256, 9);
        pack_b<<<g1, 256>>>(W1, root1, w1hi, w1lo, KW_H);
        pack_b<<<g1, 256>>>(W2, root2, w2hi, w2lo, KW_H);
        dim3 g2((KW_X * HH + 255) / 256, 1);
        pack_b<<<g2, 256>>>(Wp, nullptr, wphi, wplo, KW_X);
        dim3 g3((KW_H * HH + 255) / 256, 1);
        pack_b<<<g3, 256>>>(Wg, nullptr, wghi, wglo, KW_H);
    }
    split_mat<<<(NN * KW_X + 255) / 256, 256>>>(x, xhi, xlo, NN * KW_X);
    fill_f4<<<64, 256>>>((float4*)deg, NN * RR / 4, 0.f);
    deg_count<<<(EE + 255) / 256, 256>>>(tgt, etype, deg, EE);
    make_invdeg<<<(NN * RR + 255) / 256, 256>>>(deg, NN * RR);

    // ---- projection: hA = pack(x @ Wp + bp)
    gemm_pk<1><<<dim3(gemmGrid, 1), 256>>>(xhi, xlo, wphi, wplo, bp,
                                           nullptr, nullptr, hAhi, hAlo, NN, KW_X);

    // ---- RGCN layer 1 ----
    gemm_pk<2><<<dim3(gemmGrid, 9), 256>>>(hAhi, hAlo, w1hi, w1lo, nullptr,
                                           Y, agg, nullptr, nullptr, NN, KW_H);
    scatter_edges<<<scatGrid, 256>>>(src, tgt, etype, Y, deg, agg, EE);
    layer_fin<<<(NN * KW_H + 255) / 256, 256>>>(agg, b1, hBhi, hBlo, NN * KW_H);

    // ---- RGCN layer 2 ----
    gemm_pk<2><<<dim3(gemmGrid, 9), 256>>>(hBhi, hBlo, w2hi, w2lo, nullptr,
                                           Y, agg, nullptr, nullptr, NN, KW_H);
    scatter_edges<<<scatGrid, 256>>>(src, tgt, etype, Y, deg, agg, EE);
    layer_fin<<<(NN * KW_H + 255) / 256, 256>>>(agg, b2, hAhi, hAlo, NN * KW_H);

    // ---- GAT ----
    gemm_pk<0><<<dim3(gemmGrid, 1), 256>>>(hAhi, hAlo, wghi, wglo, nullptr,
                                           z, nullptr, nullptr, nullptr, NN, KW_H);
    att_node<<<(NN * HEADS + 255) / 256, 256>>>(z, att, asrc, atgt, NN);
    fill_f4<<<64, 256>>>((float4*)denom, NN * HEADS / 4, 0.f);
    fill_f4<<<512, 256>>>((float4*)outun, NN * HH / 4, 0.f);
    gat_fused<<<scatGrid, 256>>>(src, tgt, asrc, atgt, z, denom, outun, EE);

    // ---- finalize
    finalize<<<(NN + 7) / 8, 256>>>(outun, denom, bg, Wf, bf, out, NN);
}

// round 14
// speedup vs baseline: 1.1277x; 1.0241x over previous
#include <cuda_runtime.h>
#include <cuda_bf16.h>
#include <cuda_fp16.h>
#include <math.h>
#include <stdint.h>

// Problem constants (fixed shapes)
#define NN 50000
#define EE 800000
#define DIN 256
#define HH 128
#define RR 8
#define HEADS 8
#define DHH 16
#define OUTC 3
#define KW_H 64     // HH/2 packed words per row
#define KW_X 128    // DIN/2 packed words per row

// ---------------- scratch (device globals; no allocation allowed) ----------
__device__ uint32_t g_Yh[(size_t)NN * RR * KW_H];   // fp16x2 Y: [n][r*64+w]
__device__ float    g_agg[(size_t)NN * HH];
__device__ uint32_t g_xhi[(size_t)NN * KW_X], g_xlo[(size_t)NN * KW_X];
__device__ uint32_t g_hAhi[(size_t)NN * KW_H], g_hAlo[(size_t)NN * KW_H];
__device__ uint32_t g_hBhi[(size_t)NN * KW_H], g_hBlo[(size_t)NN * KW_H];
__device__ uint32_t g_w1hi[9 * KW_H * HH], g_w1lo[9 * KW_H * HH];   // W1[0..7] + root1
__device__ uint32_t g_w2hi[9 * KW_H * HH], g_w2lo[9 * KW_H * HH];   // W2[0..7] + root2
__device__ uint32_t g_wphi[KW_X * HH], g_wplo[KW_X * HH];
__device__ uint32_t g_wghi[KW_H * HH], g_wglo[KW_H * HH];
__device__ float    g_z[(size_t)NN * HH];
__device__ float    g_deg[(size_t)NN * RR];          // degree -> invdeg in place
__device__ float    g_asrc[(size_t)NN * HEADS];
__device__ float    g_atgt[(size_t)NN * HEADS];
__device__ float    g_denom[(size_t)NN * HEADS];
__device__ float    g_outun[(size_t)NN * HH];

// ---------------- helpers ----------------
__device__ __forceinline__ void red4(float* p, float a, float b, float c, float d) {
    asm volatile("red.global.add.v4.f32 [%0], {%1,%2,%3,%4};"
                 :: "l"(p), "f"(a), "f"(b), "f"(c), "f"(d) : "memory");
}

// split float pair (x = k even, y = k odd) into packed bf16x2 hi + lo
__device__ __forceinline__ void split2(float x, float y, uint32_t& hp, uint32_t& lp) {
    __nv_bfloat16 xh = __float2bfloat16(x);
    __nv_bfloat16 yh = __float2bfloat16(y);
    float xr = x - __bfloat162float(xh);
    float yr = y - __bfloat162float(yh);
    __nv_bfloat16 xl = __float2bfloat16(xr);
    __nv_bfloat16 yl = __float2bfloat16(yr);
    hp = ((uint32_t)__bfloat16_as_ushort(yh) << 16) | (uint32_t)__bfloat16_as_ushort(xh);
    lp = ((uint32_t)__bfloat16_as_ushort(yl) << 16) | (uint32_t)__bfloat16_as_ushort(xl);
}

__device__ __forceinline__ void mma_bf16(float& c0, float& c1, float& c2, float& c3,
                                         uint32_t a0, uint32_t a1, uint32_t a2, uint32_t a3,
                                         uint32_t b0, uint32_t b1) {
    asm volatile("mma.sync.aligned.m16n8k16.row.col.f32.bf16.bf16.f32 "
                 "{%0,%1,%2,%3}, {%4,%5,%6,%7}, {%8,%9}, {%0,%1,%2,%3};"
                 : "+f"(c0), "+f"(c1), "+f"(c2), "+f"(c3)
                 : "r"(a0), "r"(a1), "r"(a2), "r"(a3), "r"(b0), "r"(b1));
}

// ---------------- fill / pack / split kernels ----------------
__global__ void fill_f4(float4* p, int n4, float v) {
    float4 q = make_float4(v, v, v, v);
    for (int i = blockIdx.x * blockDim.x + threadIdx.x; i < n4; i += gridDim.x * blockDim.x)
        p[i] = q;
}

// pack B chunks: fp32 [2*Kw x 128] row-major -> [Kw][128] hi/lo bf16x2 (pairs along K)
__global__ void pack_b(const float* __restrict__ srcW, const float* __restrict__ srcRoot,
                       uint32_t* __restrict__ dhi, uint32_t* __restrict__ dlo, int Kw) {
    int y = blockIdx.y;
    const float* src = (srcRoot != nullptr && y == (int)gridDim.y - 1)
                       ? srcRoot : srcW + (size_t)y * Kw * 2 * HH;
    int i = blockIdx.x * blockDim.x + threadIdx.x;
    if (i >= Kw * HH) return;
    int kp = i >> 7, n = i & 127;
    float a = src[(size_t)(2 * kp) * HH + n];
    float b = src[(size_t)(2 * kp + 1) * HH + n];
    uint32_t hp, lp; split2(a, b, hp, lp);
    dhi[(size_t)y * Kw * HH + i] = hp;
    dlo[(size_t)y * Kw * HH + i] = lp;
}

// split a contiguous row-major fp32 matrix into packed hi/lo words (pairs along row)
__global__ void split_mat(const float* __restrict__ src, uint32_t* __restrict__ dhi,
                          uint32_t* __restrict__ dlo, int nwords) {
    int i = blockIdx.x * blockDim.x + threadIdx.x;
    if (i >= nwords) return;
    float2 v = ((const float2*)src)[i];
    uint32_t hp, lp; split2(v.x, v.y, hp, lp);
    dhi[i] = hp; dlo[i] = lp;
}

// ---------------- packed-operand bf16x3 tensor-core GEMM ----------------
// C[M,128] = A@B where A,B are pre-split hi/lo bf16x2 word arrays.
// EPI 0: f32 out Cf (ld=HH). EPI 1: packed hi/lo out + bias. EPI 2: rgcn dual
//        (blockIdx.y<8 -> fp16x2 Y at word-offset by*KW_H, ld=RR*KW_H;
//         by==8 -> f32 Cagg, ld=HH).
template<int EPI>
__global__ __launch_bounds__(256, 2) void gemm_pk(
    const uint32_t* __restrict__ Ahi, const uint32_t* __restrict__ Alo,
    const uint32_t* __restrict__ Bhi_base, const uint32_t* __restrict__ Blo_base,
    const float* __restrict__ bias,
    float* __restrict__ Cf, float* __restrict__ Cagg,
    uint32_t* __restrict__ Chi, uint32_t* __restrict__ Clo,
    int M, int Kw)
{
    constexpr int LDSW = 136;
    __shared__ uint32_t As_h[8][LDSW], As_l[8][LDSW];   // [kpair][row]
    __shared__ uint32_t Bs_h[8][LDSW], Bs_l[8][LDSW];   // [kpair][col]

    const int tid = threadIdx.x;
    const int lane = tid & 31;
    const int warp = tid >> 5;
    const int warp_m = warp & 3;
    const int warp_n = warp >> 2;
    const int bm = blockIdx.x * 128;
    const int by = blockIdx.y;

    const uint32_t* Bhi = Bhi_base + (size_t)by * Kw * HH;
    const uint32_t* Blo = Blo_base + (size_t)by * Kw * HH;

    const int a_row = tid & 127;
    const int a_kq = (tid >> 7) << 2;
    const int b_kp = tid >> 5;
    const int b_n4 = (tid & 31) << 2;

    const int row_g = bm + a_row;
    const bool row_ok = (row_g < M);

    const int tig = lane & 3;
    const int gid = lane >> 2;

    float c[2][8][4];
#pragma unroll
    for (int i = 0; i < 2; i++)
#pragma unroll
        for (int j = 0; j < 8; j++)
#pragma unroll
            for (int q = 0; q < 4; q++) c[i][j][q] = 0.0f;

#pragma unroll 1
    for (int kp0 = 0; kp0 < Kw; kp0 += 8) {
        uint4 vh = make_uint4(0, 0, 0, 0), vl = make_uint4(0, 0, 0, 0);
        if (row_ok) {
            vh = *(const uint4*)(Ahi + (size_t)row_g * Kw + kp0 + a_kq);
            vl = *(const uint4*)(Alo + (size_t)row_g * Kw + kp0 + a_kq);
        }
        As_h[a_kq + 0][a_row] = vh.x; As_h[a_kq + 1][a_row] = vh.y;
        As_h[a_kq + 2][a_row] = vh.z; As_h[a_kq + 3][a_row] = vh.w;
        As_l[a_kq + 0][a_row] = vl.x; As_l[a_kq + 1][a_row] = vl.y;
        As_l[a_kq + 2][a_row] = vl.z; As_l[a_kq + 3][a_row] = vl.w;
        {
            uint4 bh = *(const uint4*)(Bhi + (size_t)(kp0 + b_kp) * HH + b_n4);
            uint4 bl = *(const uint4*)(Blo + (size_t)(kp0 + b_kp) * HH + b_n4);
            *(uint4*)&Bs_h[b_kp][b_n4] = bh;
            *(uint4*)&Bs_l[b_kp][b_n4] = bl;
        }
        __syncthreads();

        uint32_t ah[2][4], al[2][4];
#pragma unroll
        for (int mt = 0; mt < 2; mt++) {
            int r = warp_m * 32 + mt * 16 + gid;
            ah[mt][0] = As_h[tig][r];     ah[mt][1] = As_h[tig][r + 8];
            ah[mt][2] = As_h[tig + 4][r]; ah[mt][3] = As_h[tig + 4][r + 8];
            al[mt][0] = As_l[tig][r];     al[mt][1] = As_l[tig][r + 8];
            al[mt][2] = As_l[tig + 4][r]; al[mt][3] = As_l[tig + 4][r + 8];
        }
#pragma unroll
        for (int half = 0; half < 2; half++) {
            uint32_t bh[4][2], bl[4][2];
#pragma unroll
            for (int n4 = 0; n4 < 4; n4++) {
                int cc = warp_n * 64 + (half * 4 + n4) * 8 + gid;
                bh[n4][0] = Bs_h[tig][cc]; bh[n4][1] = Bs_h[tig + 4][cc];
                bl[n4][0] = Bs_l[tig][cc]; bl[n4][1] = Bs_l[tig + 4][cc];
            }
#pragma unroll
            for (int mt = 0; mt < 2; mt++)
#pragma unroll
                for (int n4 = 0; n4 < 4; n4++) {
                    int nt = half * 4 + n4;
                    mma_bf16(c[mt][nt][0], c[mt][nt][1], c[mt][nt][2], c[mt][nt][3],
                             ah[mt][0], ah[mt][1], ah[mt][2], ah[mt][3],
                             bh[n4][0], bh[n4][1]);
                    mma_bf16(c[mt][nt][0], c[mt][nt][1], c[mt][nt][2], c[mt][nt][3],
                             ah[mt][0], ah[mt][1], ah[mt][2], ah[mt][3],
                             bl[n4][0], bl[n4][1]);
                    mma_bf16(c[mt][nt][0], c[mt][nt][1], c[mt][nt][2], c[mt][nt][3],
                             al[mt][0], al[mt][1], al[mt][2], al[mt][3],
                             bh[n4][0], bh[n4][1]);
                }
        }
        __syncthreads();
    }

    const int er0 = bm + warp_m * 32 + gid;
    const int ec0 = warp_n * 64 + (tig << 1);
#pragma unroll
    for (int mt = 0; mt < 2; mt++) {
#pragma unroll
        for (int half = 0; half < 2; half++) {
            int row = er0 + mt * 16 + half * 8;
            if (row >= M) continue;
#pragma unroll
            for (int nt = 0; nt < 8; nt++) {
                int col = ec0 + nt * 8;
                float v0 = c[mt][nt][half * 2 + 0];
                float v1 = c[mt][nt][half * 2 + 1];
                if (EPI == 1 && bias) { v0 += bias[col]; v1 += bias[col + 1]; }
                if (EPI == 0) {
                    *(float2*)(Cf + (size_t)row * HH + col) = make_float2(v0, v1);
                } else if (EPI == 1) {
                    uint32_t hp, lp; split2(v0, v1, hp, lp);
                    Chi[(size_t)row * KW_H + (col >> 1)] = hp;
                    Clo[(size_t)row * KW_H + (col >> 1)] = lp;
                } else {
                    if (by < 8) {
                        __half2 hv = __floats2half2_rn(v0, v1);
                        Chi[(size_t)row * (RR * KW_H) + by * KW_H + (col >> 1)] =
                            *(uint32_t*)&hv;
                    } else {
                        *(float2*)(Cagg + (size_t)row * HH + col) = make_float2(v0, v1);
                    }
                }
            }
        }
    }
}

// ---------------- degree + scatter + layer-finalize ----------------
__global__ void deg_count(const int* __restrict__ tgt, const int* __restrict__ et,
                          float* __restrict__ deg, int E) {
    int e = blockIdx.x * blockDim.x + threadIdx.x;
    if (e >= E) return;
    atomicAdd(deg + (size_t)tgt[e] * RR + et[e], 1.0f);
}

__global__ void make_invdeg(float* deg, int n) {
    int i = blockIdx.x * blockDim.x + threadIdx.x;
    if (i < n) deg[i] = 1.0f / fmaxf(deg[i], 1.0f);
}

// warp per edge: agg[tgt] += fp16(Y[src, etype]) * invdeg[tgt, etype]
__global__ void scatter_edges(const int* __restrict__ src, const int* __restrict__ tgt,
                              const int* __restrict__ et, const uint32_t* __restrict__ Yh,
                              const float* __restrict__ invdeg, float* __restrict__ agg, int E)
{
    int w = (blockIdx.x * blockDim.x + threadIdx.x) >> 5;
    int lane = threadIdx.x & 31;
    if (w >= E) return;
    int s = src[w], t = tgt[w], r = et[w];
    float iv = invdeg[(size_t)t * RR + r];
    uint2 pk = ((const uint2*)(Yh + (size_t)s * (RR * KW_H) + r * KW_H))[lane];
    float2 f0 = __half22float2(*(__half2*)&pk.x);
    float2 f1 = __half22float2(*(__half2*)&pk.y);
    red4(agg + (size_t)t * HH + lane * 4,
         f0.x * iv, f0.y * iv, f1.x * iv, f1.y * iv);
}

// h_next = relu(agg + b) -> packed hi/lo
__global__ void layer_fin(const float* __restrict__ agg, const float* __restrict__ b,
                          uint32_t* __restrict__ dhi, uint32_t* __restrict__ dlo, int nwords)
{
    int i = blockIdx.x * blockDim.x + threadIdx.x;
    if (i >= nwords) return;
    int col2 = (i & (KW_H - 1)) << 1;
    float2 v = ((const float2*)agg)[i];
    float v0 = fmaxf(v.x + b[col2], 0.f);
    float v1 = fmaxf(v.y + b[col2 + 1], 0.f);
    uint32_t hp, lp; split2(v0, v1, hp, lp);
    dhi[i] = hp; dlo[i] = lp;
}

// ---------------- GAT ----------------
__global__ void att_node(const float* __restrict__ z, const float* __restrict__ att,
                         float* __restrict__ asrc, float* __restrict__ atgt, int n)
{
    int i = blockIdx.x * blockDim.x + threadIdx.x;
    if (i >= n * HEADS) return;
    int node = i >> 3, hd = i & 7;
    const float* zp = z + (size_t)node * HH + hd * DHH;
    const float* al = att + hd * (2 * DHH);
    float sa = 0.f, sb = 0.f;
#pragma unroll
    for (int d = 0; d < DHH; d++) {
        float zv = zp[d];
        sa += zv * al[d];
        sb += zv * al[DHH + d];
    }
    asrc[i] = sa;
    atgt[i] = sb;
}

// fused single-pass GAT: no max-shift (softmax shift-invariant; alpha bounded small).
__global__ void gat_fused(const int* __restrict__ src, const int* __restrict__ tgt,
                          const float* __restrict__ asrc, const float* __restrict__ atgt,
                          const float* __restrict__ z, float* __restrict__ denom,
                          float* __restrict__ outun, int E)
{
    int w = (blockIdx.x * blockDim.x + threadIdx.x) >> 5;
    int lane = threadIdx.x & 31;
    if (w >= E) return;
    int s = src[w], t = tgt[w];
    int head = lane >> 2;
    float a = asrc[(size_t)s * HEADS + head] + atgt[(size_t)t * HEADS + head];
    a = a > 0.f ? a : 0.2f * a;
    float ex = __expf(a);
    if ((lane & 3) == 0) atomicAdd(denom + (size_t)t * HEADS + head, ex);
    float4 zv = ((const float4*)(z + (size_t)s * HH))[lane];
    red4(outun + (size_t)t * HH + lane * 4, zv.x * ex, zv.y * ex, zv.z * ex, zv.w * ex);
}

// finalize: gat-normalize + bg, then 128x3 projection, log_softmax. Warp per node.
__global__ void finalize(const float* __restrict__ outun, const float* __restrict__ denom,
                         const float* __restrict__ bg, const float* __restrict__ Wf,
                         const float* __restrict__ bf, float* __restrict__ out, int n)
{
    int w = (blockIdx.x * blockDim.x + threadIdx.x) >> 5;
    int lane = threadIdx.x & 31;
    if (w >= n) return;
    float4 g = ((const float4*)(outun + (size_t)w * HH))[lane];
    int head = lane >> 2;
    float dn = denom[(size_t)w * HEADS + head];
    float inv = 1.0f / fmaxf(dn, 1e-16f);
    float4 bgv = ((const float4*)bg)[lane];
    float gv[4] = { g.x * inv + bgv.x, g.y * inv + bgv.y,
                    g.z * inv + bgv.z, g.w * inv + bgv.w };
    float a0 = 0.f, a1 = 0.f, a2 = 0.f;
    int j0 = lane * 4;
#pragma unroll
    for (int c = 0; c < 4; c++) {
        int j = j0 + c;
        a0 += gv[c] * Wf[j * OUTC + 0];
        a1 += gv[c] * Wf[j * OUTC + 1];
        a2 += gv[c] * Wf[j * OUTC + 2];
    }
#pragma unroll
    for (int off = 16; off > 0; off >>= 1) {
        a0 += __shfl_xor_sync(0xFFFFFFFFu, a0, off);
        a1 += __shfl_xor_sync(0xFFFFFFFFu, a1, off);
        a2 += __shfl_xor_sync(0xFFFFFFFFu, a2, off);
    }
    if (lane == 0) {
        float l0 = a0 + bf[0], l1 = a1 + bf[1], l2 = a2 + bf[2];
        float m = fmaxf(l0, fmaxf(l1, l2));
        float lse = m + logf(expf(l0 - m) + expf(l1 - m) + expf(l2 - m));
        out[(size_t)w * OUTC + 0] = l0 - lse;
        out[(size_t)w * OUTC + 1] = l1 - lse;
        out[(size_t)w * OUTC + 2] = l2 - lse;
    }
}

// ---------------- launch ----------------
extern "C" void kernel_launch(void* const* d_in, const int* in_sizes, int n_in,
                              void* d_out, int out_size)
{
    const float* x     = (const float*)d_in[0];
    const int*   ei    = (const int*)d_in[1];
    const int*   etype = (const int*)d_in[2];
    const float* Wp    = (const float*)d_in[3];
    const float* bp    = (const float*)d_in[4];
    const float* W1    = (const float*)d_in[5];
    const float* root1 = (const float*)d_in[6];
    const float* b1    = (const float*)d_in[7];
    const float* W2    = (const float*)d_in[8];
    const float* root2 = (const float*)d_in[9];
    const float* b2    = (const float*)d_in[10];
    const float* Wg    = (const float*)d_in[11];
    const float* att   = (const float*)d_in[12];
    const float* bg    = (const float*)d_in[13];
    const float* Wf    = (const float*)d_in[14];
    const float* bf    = (const float*)d_in[15];
    float* out = (float*)d_out;

    const int* src = ei;
    const int* tgt = ei + EE;

    float *agg, *z, *deg, *asrc, *atgt, *denom, *outun;
    uint32_t *Yh;
    uint32_t *xhi, *xlo, *hAhi, *hAlo, *hBhi, *hBlo;
    uint32_t *w1hi, *w1lo, *w2hi, *w2lo, *wphi, *wplo, *wghi, *wglo;
    cudaGetSymbolAddress((void**)&Yh, g_Yh);
    cudaGetSymbolAddress((void**)&agg, g_agg);
    cudaGetSymbolAddress((void**)&z, g_z);
    cudaGetSymbolAddress((void**)&deg, g_deg);
    cudaGetSymbolAddress((void**)&asrc, g_asrc);
    cudaGetSymbolAddress((void**)&atgt, g_atgt);
    cudaGetSymbolAddress((void**)&denom, g_denom);
    cudaGetSymbolAddress((void**)&outun, g_outun);
    cudaGetSymbolAddress((void**)&xhi, g_xhi);
    cudaGetSymbolAddress((void**)&xlo, g_xlo);
    cudaGetSymbolAddress((void**)&hAhi, g_hAhi);
    cudaGetSymbolAddress((void**)&hAlo, g_hAlo);
    cudaGetSymbolAddress((void**)&hBhi, g_hBhi);
    cudaGetSymbolAddress((void**)&hBlo, g_hBlo);
    cudaGetSymbolAddress((void**)&w1hi, g_w1hi);
    cudaGetSymbolAddress((void**)&w1lo, g_w1lo);
    cudaGetSymbolAddress((void**)&w2hi, g_w2hi);
    cudaGetSymbolAddress((void**)&w2lo, g_w2lo);
    cudaGetSymbolAddress((void**)&wphi, g_wphi);
    cudaGetSymbolAddress((void**)&wplo, g_wplo);
    cudaGetSymbolAddress((void**)&wghi, g_wghi);
    cudaGetSymbolAddress((void**)&wglo, g_wglo);

    const int gemmGrid = (NN + 127) / 128;   // 391
    const int scatGrid = (EE + 7) / 8;

    // ---- one-time packs / splits / degrees ----
    {
        dim3 g1((KW_H * HH + 255) / 256, 9);
        pack_b<<<g1, 256>>>(W1, root1, w1hi, w1lo, KW_H);
        pack_b<<<g1, 256>>>(W2, root2, w2hi, w2lo, KW_H);
        dim3 g2((KW_X * HH + 255) / 256, 1);
        pack_b<<<g2, 256>>>(Wp, nullptr, wphi, wplo, KW_X);
        dim3 g3((KW_H * HH + 255) / 256, 1);
        pack_b<<<g3, 256>>>(Wg, nullptr, wghi, wglo, KW_H);
    }
    split_mat<<<(NN * KW_X + 255) / 256, 256>>>(x, xhi, xlo, NN * KW_X);
    fill_f4<<<64, 256>>>((float4*)deg, NN * RR / 4, 0.f);
    deg_count<<<(EE + 255) / 256, 256>>>(tgt, etype, deg, EE);
    make_invdeg<<<(NN * RR + 255) / 256, 256>>>(deg, NN * RR);

    // ---- projection: hA = pack(x @ Wp + bp)
    gemm_pk<1><<<dim3(gemmGrid, 1), 256>>>(xhi, xlo, wphi, wplo, bp,
                                           nullptr, nullptr, hAhi, hAlo, NN, KW_X);

    // ---- RGCN layer 1 ----
    gemm_pk<2><<<dim3(gemmGrid, 9), 256>>>(hAhi, hAlo, w1hi, w1lo, nullptr,
                                           nullptr, agg, Yh, nullptr, NN, KW_H);
    scatter_edges<<<scatGrid, 256>>>(src, tgt, etype, Yh, deg, agg, EE);
    layer_fin<<<(NN * KW_H + 255) / 256, 256>>>(agg, b1, hBhi, hBlo, NN * KW_H);

    // ---- RGCN layer 2 ----
    gemm_pk<2><<<dim3(gemmGrid, 9), 256>>>(hBhi, hBlo, w2hi, w2lo, nullptr,
                                           nullptr, agg, Yh, nullptr, NN, KW_H);
    scatter_edges<<<scatGrid, 256>>>(src, tgt, etype, Yh, deg, agg, EE);
    layer_fin<<<(NN * KW_H + 255) / 256, 256>>>(agg, b2, hAhi, hAlo, NN * KW_H);

    // ---- GAT ----
    gemm_pk<0><<<dim3(gemmGrid, 1), 256>>>(hAhi, hAlo, wghi, wglo, nullptr,
                                           z, nullptr, nullptr, nullptr, NN, KW_H);
    att_node<<<(NN * HEADS + 255) / 256, 256>>>(z, att, asrc, atgt, NN);
    fill_f4<<<64, 256>>>((float4*)denom, NN * HEADS / 4, 0.f);
    fill_f4<<<512, 256>>>((float4*)outun, NN * HH / 4, 0.f);
    gat_fused<<<scatGrid, 256>>>(src, tgt, asrc, atgt, z, denom, outun, EE);

    // ---- finalize
    finalize<<<(NN + 7) / 8, 256>>>(outun, denom, bg, Wf, bf, out, NN);
}

// round 15
// speedup vs baseline: 1.4521x; 1.2877x over previous
#include <cuda_runtime.h>
#include <cuda_bf16.h>
#include <cuda_fp16.h>
#include <math.h>
#include <stdint.h>

// Problem constants (fixed shapes)
#define NN 50000
#define EE 800000
#define DIN 256
#define HH 128
#define RR 8
#define HEADS 8
#define DHH 16
#define OUTC 3
#define KW_H 64     // HH/2 packed words per row
#define KW_X 128    // DIN/2 packed words per row

// ---------------- scratch (device globals; no allocation allowed) ----------
__device__ uint32_t g_Yh[(size_t)NN * RR * KW_H];   // fp16x2 Y: [n][r*64+w]
__device__ float    g_agg[(size_t)NN * HH];
__device__ uint32_t g_xhi[(size_t)NN * KW_X], g_xlo[(size_t)NN * KW_X];
__device__ uint32_t g_hAhi[(size_t)NN * KW_H], g_hAlo[(size_t)NN * KW_H];
__device__ uint32_t g_hBhi[(size_t)NN * KW_H], g_hBlo[(size_t)NN * KW_H];
__device__ uint32_t g_w1hi[9 * KW_H * HH], g_w1lo[9 * KW_H * HH];   // W1[0..7] + root1
__device__ uint32_t g_w2hi[9 * KW_H * HH], g_w2lo[9 * KW_H * HH];   // W2[0..7] + root2
__device__ uint32_t g_wphi[KW_X * HH], g_wplo[KW_X * HH];
__device__ uint32_t g_wghi[KW_H * HH], g_wglo[KW_H * HH];
__device__ float    g_z[(size_t)NN * HH];
__device__ float    g_deg[(size_t)NN * RR];          // degree -> invdeg in place
__device__ float    g_asrc[(size_t)NN * HEADS];
__device__ float    g_atgt[(size_t)NN * HEADS];
// CSR by target
__device__ int      g_cnt[NN];                       // per-tgt edge count
__device__ int      g_rs[NN];                        // row start (excl scan)
__device__ int      g_cur[NN];                       // fill cursors
__device__ int      g_bsum[256];                     // block partial sums
__device__ int2     g_eidx[(size_t)EE];              // (src, r) sorted by tgt

// ---------------- helpers ----------------
// split float pair into packed bf16x2 hi + lo
__device__ __forceinline__ void split2(float x, float y, uint32_t& hp, uint32_t& lp) {
    __nv_bfloat16 xh = __float2bfloat16(x);
    __nv_bfloat16 yh = __float2bfloat16(y);
    float xr = x - __bfloat162float(xh);
    float yr = y - __bfloat162float(yh);
    __nv_bfloat16 xl = __float2bfloat16(xr);
    __nv_bfloat16 yl = __float2bfloat16(yr);
    hp = ((uint32_t)__bfloat16_as_ushort(yh) << 16) | (uint32_t)__bfloat16_as_ushort(xh);
    lp = ((uint32_t)__bfloat16_as_ushort(yl) << 16) | (uint32_t)__bfloat16_as_ushort(xl);
}

__device__ __forceinline__ void mma_bf16(float& c0, float& c1, float& c2, float& c3,
                                         uint32_t a0, uint32_t a1, uint32_t a2, uint32_t a3,
                                         uint32_t b0, uint32_t b1) {
    asm volatile("mma.sync.aligned.m16n8k16.row.col.f32.bf16.bf16.f32 "
                 "{%0,%1,%2,%3}, {%4,%5,%6,%7}, {%8,%9}, {%0,%1,%2,%3};"
                 : "+f"(c0), "+f"(c1), "+f"(c2), "+f"(c3)
                 : "r"(a0), "r"(a1), "r"(a2), "r"(a3), "r"(b0), "r"(b1));
}

// ---------------- fill / pack / split kernels ----------------
__global__ void fill_f4(float4* p, int n4, float v) {
    float4 q = make_float4(v, v, v, v);
    for (int i = blockIdx.x * blockDim.x + threadIdx.x; i < n4; i += gridDim.x * blockDim.x)
        p[i] = q;
}
__global__ void fill_i(int* p, int n, int v) {
    int i = blockIdx.x * blockDim.x + threadIdx.x;
    if (i < n) p[i] = v;
}

// pack B chunks: fp32 [2*Kw x 128] row-major -> [Kw][128] hi/lo bf16x2 (pairs along K)
__global__ void pack_b(const float* __restrict__ srcW, const float* __restrict__ srcRoot,
                       uint32_t* __restrict__ dhi, uint32_t* __restrict__ dlo, int Kw) {
    int y = blockIdx.y;
    const float* src = (srcRoot != nullptr && y == (int)gridDim.y - 1)
                       ? srcRoot : srcW + (size_t)y * Kw * 2 * HH;
    int i = blockIdx.x * blockDim.x + threadIdx.x;
    if (i >= Kw * HH) return;
    int kp = i >> 7, n = i & 127;
    float a = src[(size_t)(2 * kp) * HH + n];
    float b = src[(size_t)(2 * kp + 1) * HH + n];
    uint32_t hp, lp; split2(a, b, hp, lp);
    dhi[(size_t)y * Kw * HH + i] = hp;
    dlo[(size_t)y * Kw * HH + i] = lp;
}

// split a contiguous row-major fp32 matrix into packed hi/lo words
__global__ void split_mat(const float* __restrict__ src, uint32_t* __restrict__ dhi,
                          uint32_t* __restrict__ dlo, int nwords) {
    int i = blockIdx.x * blockDim.x + threadIdx.x;
    if (i >= nwords) return;
    float2 v = ((const float2*)src)[i];
    uint32_t hp, lp; split2(v.x, v.y, hp, lp);
    dhi[i] = hp; dlo[i] = lp;
}

// ---------------- CSR build (counting sort by tgt) ----------------
__global__ void hist_tgt(const int* __restrict__ tgt, int* __restrict__ cnt, int E) {
    int e = blockIdx.x * blockDim.x + threadIdx.x;
    if (e < E) atomicAdd(&cnt[tgt[e]], 1);
}
__global__ void scanA(const int* __restrict__ cnt, int* __restrict__ incl,
                      int* __restrict__ bsum, int n) {
    __shared__ int s[256];
    int i = blockIdx.x * 256 + threadIdx.x;
    int v = (i < n) ? cnt[i] : 0;
    s[threadIdx.x] = v;
    __syncthreads();
#pragma unroll
    for (int off = 1; off < 256; off <<= 1) {
        int t = (threadIdx.x >= off) ? s[threadIdx.x - off] : 0;
        __syncthreads();
        s[threadIdx.x] += t;
        __syncthreads();
    }
    if (i < n) incl[i] = s[threadIdx.x];
    if (threadIdx.x == 255) bsum[blockIdx.x] = s[255];
}
__global__ void scanB(int* __restrict__ bsum, int nb) {
    __shared__ int s[256];
    int v = (threadIdx.x < nb) ? bsum[threadIdx.x] : 0;
    s[threadIdx.x] = v;
    __syncthreads();
#pragma unroll
    for (int off = 1; off < 256; off <<= 1) {
        int t = (threadIdx.x >= off) ? s[threadIdx.x - off] : 0;
        __syncthreads();
        s[threadIdx.x] += t;
        __syncthreads();
    }
    if (threadIdx.x < nb) bsum[threadIdx.x] = s[threadIdx.x] - v;  // exclusive
}
__global__ void scanC(int* __restrict__ rs_incl, const int* __restrict__ cnt,
                      const int* __restrict__ boff, int* __restrict__ cur, int n) {
    int i = blockIdx.x * blockDim.x + threadIdx.x;
    if (i >= n) return;
    int v = rs_incl[i] - cnt[i] + boff[i >> 8];
    rs_incl[i] = v;
    cur[i] = v;
}
__global__ void fill_edges(const int* __restrict__ src, const int* __restrict__ tgt,
                           const int* __restrict__ et, int* __restrict__ cur,
                           int2* __restrict__ eidx, int E) {
    int e = blockIdx.x * blockDim.x + threadIdx.x;
    if (e >= E) return;
    int t = tgt[e];
    int slot = atomicAdd(&cur[t], 1);
    eidx[slot] = make_int2(src[e], et[e]);
}

// ---------------- packed-operand bf16x3 tensor-core GEMM ----------------
// EPI 0: f32 out Cf. EPI 1: packed hi/lo out + bias. EPI 2: rgcn dual
//        (by<8 -> fp16x2 Y; by==8 -> f32 Cagg).
template<int EPI>
__global__ __launch_bounds__(256, 2) void gemm_pk(
    const uint32_t* __restrict__ Ahi, const uint32_t* __restrict__ Alo,
    const uint32_t* __restrict__ Bhi_base, const uint32_t* __restrict__ Blo_base,
    const float* __restrict__ bias,
    float* __restrict__ Cf, float* __restrict__ Cagg,
    uint32_t* __restrict__ Chi, uint32_t* __restrict__ Clo,
    int M, int Kw)
{
    constexpr int LDSW = 136;
    __shared__ uint32_t As_h[8][LDSW], As_l[8][LDSW];
    __shared__ uint32_t Bs_h[8][LDSW], Bs_l[8][LDSW];

    const int tid = threadIdx.x;
    const int lane = tid & 31;
    const int warp = tid >> 5;
    const int warp_m = warp & 3;
    const int warp_n = warp >> 2;
    const int bm = blockIdx.x * 128;
    const int by = blockIdx.y;

    const uint32_t* Bhi = Bhi_base + (size_t)by * Kw * HH;
    const uint32_t* Blo = Blo_base + (size_t)by * Kw * HH;

    const int a_row = tid & 127;
    const int a_kq = (tid >> 7) << 2;
    const int b_kp = tid >> 5;
    const int b_n4 = (tid & 31) << 2;

    const int row_g = bm + a_row;
    const bool row_ok = (row_g < M);

    const int tig = lane & 3;
    const int gid = lane >> 2;

    float c[2][8][4];
#pragma unroll
    for (int i = 0; i < 2; i++)
#pragma unroll
        for (int j = 0; j < 8; j++)
#pragma unroll
            for (int q = 0; q < 4; q++) c[i][j][q] = 0.0f;

#pragma unroll 1
    for (int kp0 = 0; kp0 < Kw; kp0 += 8) {
        uint4 vh = make_uint4(0, 0, 0, 0), vl = make_uint4(0, 0, 0, 0);
        if (row_ok) {
            vh = *(const uint4*)(Ahi + (size_t)row_g * Kw + kp0 + a_kq);
            vl = *(const uint4*)(Alo + (size_t)row_g * Kw + kp0 + a_kq);
        }
        As_h[a_kq + 0][a_row] = vh.x; As_h[a_kq + 1][a_row] = vh.y;
        As_h[a_kq + 2][a_row] = vh.z; As_h[a_kq + 3][a_row] = vh.w;
        As_l[a_kq + 0][a_row] = vl.x; As_l[a_kq + 1][a_row] = vl.y;
        As_l[a_kq + 2][a_row] = vl.z; As_l[a_kq + 3][a_row] = vl.w;
        {
            uint4 bh = *(const uint4*)(Bhi + (size_t)(kp0 + b_kp) * HH + b_n4);
            uint4 bl = *(const uint4*)(Blo + (size_t)(kp0 + b_kp) * HH + b_n4);
            *(uint4*)&Bs_h[b_kp][b_n4] = bh;
            *(uint4*)&Bs_l[b_kp][b_n4] = bl;
        }
        __syncthreads();

        uint32_t ah[2][4], al[2][4];
#pragma unroll
        for (int mt = 0; mt < 2; mt++) {
            int r = warp_m * 32 + mt * 16 + gid;
            ah[mt][0] = As_h[tig][r];     ah[mt][1] = As_h[tig][r + 8];
            ah[mt][2] = As_h[tig + 4][r]; ah[mt][3] = As_h[tig + 4][r + 8];
            al[mt][0] = As_l[tig][r];     al[mt][1] = As_l[tig][r + 8];
            al[mt][2] = As_l[tig + 4][r]; al[mt][3] = As_l[tig + 4][r + 8];
        }
#pragma unroll
        for (int half = 0; half < 2; half++) {
            uint32_t bh[4][2], bl[4][2];
#pragma unroll
            for (int n4 = 0; n4 < 4; n4++) {
                int cc = warp_n * 64 + (half * 4 + n4) * 8 + gid;
                bh[n4][0] = Bs_h[tig][cc]; bh[n4][1] = Bs_h[tig + 4][cc];
                bl[n4][0] = Bs_l[tig][cc]; bl[n4][1] = Bs_l[tig + 4][cc];
            }
#pragma unroll
            for (int mt = 0; mt < 2; mt++)
#pragma unroll
                for (int n4 = 0; n4 < 4; n4++) {
                    int nt = half * 4 + n4;
                    mma_bf16(c[mt][nt][0], c[mt][nt][1], c[mt][nt][2], c[mt][nt][3],
                             ah[mt][0], ah[mt][1], ah[mt][2], ah[mt][3],
                             bh[n4][0], bh[n4][1]);
                    mma_bf16(c[mt][nt][0], c[mt][nt][1], c[mt][nt][2], c[mt][nt][3],
                             ah[mt][0], ah[mt][1], ah[mt][2], ah[mt][3],
                             bl[n4][0], bl[n4][1]);
                    mma_bf16(c[mt][nt][0], c[mt][nt][1], c[mt][nt][2], c[mt][nt][3],
                             al[mt][0], al[mt][1], al[mt][2], al[mt][3],
                             bh[n4][0], bh[n4][1]);
                }
        }
        __syncthreads();
    }

    const int er0 = bm + warp_m * 32 + gid;
    const int ec0 = warp_n * 64 + (tig << 1);
#pragma unroll
    for (int mt = 0; mt < 2; mt++) {
#pragma unroll
        for (int half = 0; half < 2; half++) {
            int row = er0 + mt * 16 + half * 8;
            if (row >= M) continue;
#pragma unroll
            for (int nt = 0; nt < 8; nt++) {
                int col = ec0 + nt * 8;
                float v0 = c[mt][nt][half * 2 + 0];
                float v1 = c[mt][nt][half * 2 + 1];
                if (EPI == 1 && bias) { v0 += bias[col]; v1 += bias[col + 1]; }
                if (EPI == 0) {
                    *(float2*)(Cf + (size_t)row * HH + col) = make_float2(v0, v1);
                } else if (EPI == 1) {
                    uint32_t hp, lp; split2(v0, v1, hp, lp);
                    Chi[(size_t)row * KW_H + (col >> 1)] = hp;
                    Clo[(size_t)row * KW_H + (col >> 1)] = lp;
                } else {
                    if (by < 8) {
                        __half2 hv = __floats2half2_rn(v0, v1);
                        Chi[(size_t)row * (RR * KW_H) + by * KW_H + (col >> 1)] =
                            *(uint32_t*)&hv;
                    } else {
                        *(float2*)(Cagg + (size_t)row * HH + col) = make_float2(v0, v1);
                    }
                }
            }
        }
    }
}

// ---------------- degree ----------------
__global__ void deg_count(const int* __restrict__ tgt, const int* __restrict__ et,
                          float* __restrict__ deg, int E) {
    int e = blockIdx.x * blockDim.x + threadIdx.x;
    if (e >= E) return;
    atomicAdd(deg + (size_t)tgt[e] * RR + et[e], 1.0f);
}
__global__ void make_invdeg(float* deg, int n) {
    int i = blockIdx.x * blockDim.x + threadIdx.x;
    if (i < n) deg[i] = 1.0f / fmaxf(deg[i], 1.0f);
}

// ---------------- RGCN gather: warp per target node ----------------
// acc = agg_root[n] + sum_e fp16(Y[src_e, r_e]) * invdeg[n, r_e]
// then h_next = relu(acc + b) packed to hi/lo (fuses layer_fin).
__global__ void rgcn_gather(const int2* __restrict__ eidx, const int* __restrict__ rs,
                            const int* __restrict__ cnt, const uint32_t* __restrict__ Yh,
                            const float* __restrict__ invdeg, const float* __restrict__ aggroot,
                            const float* __restrict__ b,
                            uint32_t* __restrict__ dhi, uint32_t* __restrict__ dlo, int n)
{
    int w = (blockIdx.x * blockDim.x + threadIdx.x) >> 5;
    int lane = threadIdx.x & 31;
    if (w >= n) return;
    float4 a0 = ((const float4*)(aggroot + (size_t)w * HH))[lane];
    float acc[4] = { a0.x, a0.y, a0.z, a0.w };
    int s0 = rs[w], e1 = s0 + cnt[w];
#pragma unroll 2
    for (int e = s0; e < e1; e++) {
        int2 p = eidx[e];
        float iv = invdeg[(size_t)w * RR + p.y];
        uint2 pk = ((const uint2*)(Yh + ((size_t)p.x * RR + p.y) * KW_H))[lane];
        float2 f0 = __half22float2(*(__half2*)&pk.x);
        float2 f1 = __half22float2(*(__half2*)&pk.y);
        acc[0] += f0.x * iv; acc[1] += f0.y * iv;
        acc[2] += f1.x * iv; acc[3] += f1.y * iv;
    }
    int col = lane * 4;
    float v0 = fmaxf(acc[0] + b[col + 0], 0.f);
    float v1 = fmaxf(acc[1] + b[col + 1], 0.f);
    float v2 = fmaxf(acc[2] + b[col + 2], 0.f);
    float v3 = fmaxf(acc[3] + b[col + 3], 0.f);
    uint32_t h0, l0, h1, l1;
    split2(v0, v1, h0, l0);
    split2(v2, v3, h1, l1);
    ((uint2*)(dhi + (size_t)w * KW_H))[lane] = make_uint2(h0, h1);
    ((uint2*)(dlo + (size_t)w * KW_H))[lane] = make_uint2(l0, l1);
}

// ---------------- GAT ----------------
__global__ void att_node(const float* __restrict__ z, const float* __restrict__ att,
                         float* __restrict__ asrc, float* __restrict__ atgt, int n)
{
    int i = blockIdx.x * blockDim.x + threadIdx.x;
    if (i >= n * HEADS) return;
    int node = i >> 3, hd = i & 7;
    const float* zp = z + (size_t)node * HH + hd * DHH;
    const float* al = att + hd * (2 * DHH);
    float sa = 0.f, sb = 0.f;
#pragma unroll
    for (int d = 0; d < DHH; d++) {
        float zv = zp[d];
        sa += zv * al[d];
        sb += zv * al[DHH + d];
    }
    asrc[i] = sa;
    atgt[i] = sb;
}

// fused GAT gather + normalize + bg + Wf projection + log_softmax.
// warp per target node; no max-shift (softmax shift-invariant; alpha bounded).
__global__ void gat_gather(const int2* __restrict__ eidx, const int* __restrict__ rs,
                           const int* __restrict__ cnt,
                           const float* __restrict__ asrc, const float* __restrict__ atgt,
                           const float* __restrict__ z, const float* __restrict__ bg,
                           const float* __restrict__ Wf, const float* __restrict__ bf,
                           float* __restrict__ out, int n)
{
    int w = (blockIdx.x * blockDim.x + threadIdx.x) >> 5;
    int lane = threadIdx.x & 31;
    if (w >= n) return;
    int head = lane >> 2;
    float at = atgt[(size_t)w * HEADS + head];
    float acc[4] = { 0.f, 0.f, 0.f, 0.f };
    float den = 0.f;
    int s0 = rs[w], e1 = s0 + cnt[w];
#pragma unroll 2
    for (int e = s0; e < e1; e++) {
        int s = eidx[e].x;
        float a = asrc[(size_t)s * HEADS + head] + at;
        a = a > 0.f ? a : 0.2f * a;
        float ex = __expf(a);
        den += ex;
        float4 zv = ((const float4*)(z + (size_t)s * HH))[lane];
        acc[0] += zv.x * ex; acc[1] += zv.y * ex;
        acc[2] += zv.z * ex; acc[3] += zv.w * ex;
    }
    float inv = 1.0f / fmaxf(den, 1e-16f);
    float4 bgv = ((const float4*)bg)[lane];
    float gv[4] = { acc[0] * inv + bgv.x, acc[1] * inv + bgv.y,
                    acc[2] * inv + bgv.z, acc[3] * inv + bgv.w };
    float a0 = 0.f, a1 = 0.f, a2 = 0.f;
    int j0 = lane * 4;
#pragma unroll
    for (int c = 0; c < 4; c++) {
        int j = j0 + c;
        a0 += gv[c] * Wf[j * OUTC + 0];
        a1 += gv[c] * Wf[j * OUTC + 1];
        a2 += gv[c] * Wf[j * OUTC + 2];
    }
#pragma unroll
    for (int off = 16; off > 0; off >>= 1) {
        a0 += __shfl_xor_sync(0xFFFFFFFFu, a0, off);
        a1 += __shfl_xor_sync(0xFFFFFFFFu, a1, off);
        a2 += __shfl_xor_sync(0xFFFFFFFFu, a2, off);
    }
    if (lane == 0) {
        float l0 = a0 + bf[0], l1 = a1 + bf[1], l2 = a2 + bf[2];
        float m = fmaxf(l0, fmaxf(l1, l2));
        float lse = m + logf(expf(l0 - m) + expf(l1 - m) + expf(l2 - m));
        out[(size_t)w * OUTC + 0] = l0 - lse;
        out[(size_t)w * OUTC + 1] = l1 - lse;
        out[(size_t)w * OUTC + 2] = l2 - lse;
    }
}

// ---------------- launch ----------------
extern "C" void kernel_launch(void* const* d_in, const int* in_sizes, int n_in,
                              void* d_out, int out_size)
{
    const float* x     = (const float*)d_in[0];
    const int*   ei    = (const int*)d_in[1];
    const int*   etype = (const int*)d_in[2];
    const float* Wp    = (const float*)d_in[3];
    const float* bp    = (const float*)d_in[4];
    const float* W1    = (const float*)d_in[5];
    const float* root1 = (const float*)d_in[6];
    const float* b1    = (const float*)d_in[7];
    const float* W2    = (const float*)d_in[8];
    const float* root2 = (const float*)d_in[9];
    const float* b2    = (const float*)d_in[10];
    const float* Wg    = (const float*)d_in[11];
    const float* att   = (const float*)d_in[12];
    const float* bg    = (const float*)d_in[13];
    const float* Wf    = (const float*)d_in[14];
    const float* bf    = (const float*)d_in[15];
    float* out = (float*)d_out;

    const int* src = ei;
    const int* tgt = ei + EE;

    float *agg, *z, *deg, *asrc, *atgt;
    uint32_t *Yh;
    uint32_t *xhi, *xlo, *hAhi, *hAlo, *hBhi, *hBlo;
    uint32_t *w1hi, *w1lo, *w2hi, *w2lo, *wphi, *wplo, *wghi, *wglo;
    int *cnt, *rs, *cur, *bsum;
    int2* eidx;
    cudaGetSymbolAddress((void**)&Yh, g_Yh);
    cudaGetSymbolAddress((void**)&agg, g_agg);
    cudaGetSymbolAddress((void**)&z, g_z);
    cudaGetSymbolAddress((void**)&deg, g_deg);
    cudaGetSymbolAddress((void**)&asrc, g_asrc);
    cudaGetSymbolAddress((void**)&atgt, g_atgt);
    cudaGetSymbolAddress((void**)&xhi, g_xhi);
    cudaGetSymbolAddress((void**)&xlo, g_xlo);
    cudaGetSymbolAddress((void**)&hAhi, g_hAhi);
    cudaGetSymbolAddress((void**)&hAlo, g_hAlo);
    cudaGetSymbolAddress((void**)&hBhi, g_hBhi);
    cudaGetSymbolAddress((void**)&hBlo, g_hBlo);
    cudaGetSymbolAddress((void**)&w1hi, g_w1hi);
    cudaGetSymbolAddress((void**)&w1lo, g_w1lo);
    cudaGetSymbolAddress((void**)&w2hi, g_w2hi);
    cudaGetSymbolAddress((void**)&w2lo, g_w2lo);
    cudaGetSymbolAddress((void**)&wphi, g_wphi);
    cudaGetSymbolAddress((void**)&wplo, g_wplo);
    cudaGetSymbolAddress((void**)&wghi, g_wghi);
    cudaGetSymbolAddress((void**)&wglo, g_wglo);
    cudaGetSymbolAddress((void**)&cnt, g_cnt);
    cudaGetSymbolAddress((void**)&rs, g_rs);
    cudaGetSymbolAddress((void**)&cur, g_cur);
    cudaGetSymbolAddress((void**)&bsum, g_bsum);
    cudaGetSymbolAddress((void**)&eidx, g_eidx);

    const int gemmGrid = (NN + 127) / 128;         // 391
    const int nodeGrid = (NN * 32 + 255) / 256;    // warp per node
    const int NB = (NN + 255) / 256;               // 196 scan blocks

    // ---- one-time packs / splits / degrees / CSR ----
    {
        dim3 g1((KW_H * HH + 255) / 256, 9);
        pack_b<<<g1, 256>>>(W1, root1, w1hi, w1lo, KW_H);
        pack_b<<<g1, 256>>>(W2, root2, w2hi, w2lo, KW_H);
        dim3 g2((KW_X * HH + 255) / 256, 1);
        pack_b<<<g2, 256>>>(Wp, nullptr, wphi, wplo, KW_X);
        dim3 g3((KW_H * HH + 255) / 256, 1);
        pack_b<<<g3, 256>>>(Wg, nullptr, wghi, wglo, KW_H);
    }
    split_mat<<<(NN * KW_X + 255) / 256, 256>>>(x, xhi, xlo, NN * KW_X);
    fill_f4<<<64, 256>>>((float4*)deg, NN * RR / 4, 0.f);
    deg_count<<<(EE + 255) / 256, 256>>>(tgt, etype, deg, EE);
    make_invdeg<<<(NN * RR + 255) / 256, 256>>>(deg, NN * RR);
    // CSR by tgt
    fill_i<<<NB, 256>>>(cnt, NN, 0);
    hist_tgt<<<(EE + 255) / 256, 256>>>(tgt, cnt, EE);
    scanA<<<NB, 256>>>(cnt, rs, bsum, NN);
    scanB<<<1, 256>>>(bsum, NB);
    scanC<<<NB, 256>>>(rs, cnt, bsum, cur, NN);
    fill_edges<<<(EE + 255) / 256, 256>>>(src, tgt, etype, cur, eidx, EE);

    // ---- projection: hA = pack(x @ Wp + bp)
    gemm_pk<1><<<dim3(gemmGrid, 1), 256>>>(xhi, xlo, wphi, wplo, bp,
                                           nullptr, nullptr, hAhi, hAlo, NN, KW_X);

    // ---- RGCN layer 1 ----
    gemm_pk<2><<<dim3(gemmGrid, 9), 256>>>(hAhi, hAlo, w1hi, w1lo, nullptr,
                                           nullptr, agg, Yh, nullptr, NN, KW_H);
    rgcn_gather<<<nodeGrid, 256>>>(eidx, rs, cnt, Yh, deg, agg, b1, hBhi, hBlo, NN);

    // ---- RGCN layer 2 ----
    gemm_pk<2><<<dim3(gemmGrid, 9), 256>>>(hBhi, hBlo, w2hi, w2lo, nullptr,
                                           nullptr, agg, Yh, nullptr, NN, KW_H);
    rgcn_gather<<<nodeGrid, 256>>>(eidx, rs, cnt, Yh, deg, agg, b2, hAhi, hAlo, NN);

    // ---- GAT ----
    gemm_pk<0><<<dim3(gemmGrid, 1), 256>>>(hAhi, hAlo, wghi, wglo, nullptr,
                                           z, nullptr, nullptr, nullptr, NN, KW_H);
    att_node<<<(NN * HEADS + 255) / 256, 256>>>(z, att, asrc, atgt, NN);
    gat_gather<<<nodeGrid, 256>>>(eidx, rs, cnt, asrc, atgt, z, bg, Wf, bf, out, NN);
}

// round 16
// speedup vs baseline: 1.6111x; 1.1095x over previous
#include <cuda_runtime.h>
#include <cuda_bf16.h>
#include <cuda_fp16.h>
#include <math.h>
#include <stdint.h>

// Problem constants (fixed shapes)
#define NN 50000
#define EE 800000
#define DIN 256
#define HH 128
#define RR 8
#define HEADS 8
#define DHH 16
#define OUTC 3
#define KW_H 64     // HH/2 packed words per row
#define KW_X 128    // DIN/2 packed words per row

// ---------------- scratch (device globals; no allocation allowed) ----------
__device__ uint32_t g_Yh[(size_t)NN * RR * KW_H];   // fp16x2 Y: [n][r*64+w]
__device__ float    g_agg[(size_t)NN * HH];
__device__ uint32_t g_xhi[(size_t)NN * KW_X], g_xlo[(size_t)NN * KW_X];
__device__ uint32_t g_hAhi[(size_t)NN * KW_H], g_hAlo[(size_t)NN * KW_H];
__device__ uint32_t g_hBhi[(size_t)NN * KW_H], g_hBlo[(size_t)NN * KW_H];
__device__ uint32_t g_w1hi[9 * KW_H * HH], g_w1lo[9 * KW_H * HH];   // W1[0..7] + root1
__device__ uint32_t g_w2hi[9 * KW_H * HH], g_w2lo[9 * KW_H * HH];   // W2[0..7] + root2
__device__ uint32_t g_wphi[KW_X * HH], g_wplo[KW_X * HH];
__device__ uint32_t g_wghi[KW_H * HH], g_wglo[KW_H * HH];
__device__ float    g_z[(size_t)NN * HH];
__device__ float    g_deg[(size_t)NN * RR];          // degree -> invdeg in place
__device__ float    g_asrc[(size_t)NN * HEADS];
__device__ float    g_atgt[(size_t)NN * HEADS];
// CSR by target
__device__ int      g_cnt[NN];
__device__ int      g_rs[NN];
__device__ int      g_cur[NN];
__device__ int      g_bsum[256];
__device__ int2     g_eidx[(size_t)EE];              // (src, r) sorted by tgt

// ---------------- helpers ----------------
__device__ __forceinline__ void split2(float x, float y, uint32_t& hp, uint32_t& lp) {
    __nv_bfloat16 xh = __float2bfloat16(x);
    __nv_bfloat16 yh = __float2bfloat16(y);
    float xr = x - __bfloat162float(xh);
    float yr = y - __bfloat162float(yh);
    __nv_bfloat16 xl = __float2bfloat16(xr);
    __nv_bfloat16 yl = __float2bfloat16(yr);
    hp = ((uint32_t)__bfloat16_as_ushort(yh) << 16) | (uint32_t)__bfloat16_as_ushort(xh);
    lp = ((uint32_t)__bfloat16_as_ushort(yl) << 16) | (uint32_t)__bfloat16_as_ushort(xl);
}

__device__ __forceinline__ void mma_bf16(float& c0, float& c1, float& c2, float& c3,
                                         uint32_t a0, uint32_t a1, uint32_t a2, uint32_t a3,
                                         uint32_t b0, uint32_t b1) {
    asm volatile("mma.sync.aligned.m16n8k16.row.col.f32.bf16.bf16.f32 "
                 "{%0,%1,%2,%3}, {%4,%5,%6,%7}, {%8,%9}, {%0,%1,%2,%3};"
                 : "+f"(c0), "+f"(c1), "+f"(c2), "+f"(c3)
                 : "r"(a0), "r"(a1), "r"(a2), "r"(a3), "r"(b0), "r"(b1));
}

__device__ __forceinline__ void cpa16(uint32_t dst_s, const void* src, bool ok) {
    asm volatile("cp.async.cg.shared.global [%0], [%1], 16, %2;"
                 :: "r"(dst_s), "l"(src), "r"(ok ? 16 : 0) : "memory");
}

// ---------------- fill / pack / split kernels ----------------
__global__ void fill_f4(float4* p, int n4, float v) {
    float4 q = make_float4(v, v, v, v);
    for (int i = blockIdx.x * blockDim.x + threadIdx.x; i < n4; i += gridDim.x * blockDim.x)
        p[i] = q;
}
__global__ void fill_i(int* p, int n, int v) {
    int i = blockIdx.x * blockDim.x + threadIdx.x;
    if (i < n) p[i] = v;
}

__global__ void pack_b(const float* __restrict__ srcW, const float* __restrict__ srcRoot,
                       uint32_t* __restrict__ dhi, uint32_t* __restrict__ dlo, int Kw) {
    int y = blockIdx.y;
    const float* src = (srcRoot != nullptr && y == (int)gridDim.y - 1)
                       ? srcRoot : srcW + (size_t)y * Kw * 2 * HH;
    int i = blockIdx.x * blockDim.x + threadIdx.x;
    if (i >= Kw * HH) return;
    int kp = i >> 7, n = i & 127;
    float a = src[(size_t)(2 * kp) * HH + n];
    float b = src[(size_t)(2 * kp + 1) * HH + n];
    uint32_t hp, lp; split2(a, b, hp, lp);
    dhi[(size_t)y * Kw * HH + i] = hp;
    dlo[(size_t)y * Kw * HH + i] = lp;
}

__global__ void split_mat(const float* __restrict__ src, uint32_t* __restrict__ dhi,
                          uint32_t* __restrict__ dlo, int nwords) {
    int i = blockIdx.x * blockDim.x + threadIdx.x;
    if (i >= nwords) return;
    float2 v = ((const float2*)src)[i];
    uint32_t hp, lp; split2(v.x, v.y, hp, lp);
    dhi[i] = hp; dlo[i] = lp;
}

// ---------------- CSR build (counting sort by tgt) ----------------
__global__ void hist_tgt(const int* __restrict__ tgt, int* __restrict__ cnt, int E) {
    int e = blockIdx.x * blockDim.x + threadIdx.x;
    if (e < E) atomicAdd(&cnt[tgt[e]], 1);
}
__global__ void scanA(const int* __restrict__ cnt, int* __restrict__ incl,
                      int* __restrict__ bsum, int n) {
    __shared__ int s[256];
    int i = blockIdx.x * 256 + threadIdx.x;
    int v = (i < n) ? cnt[i] : 0;
    s[threadIdx.x] = v;
    __syncthreads();
#pragma unroll
    for (int off = 1; off < 256; off <<= 1) {
        int t = (threadIdx.x >= off) ? s[threadIdx.x - off] : 0;
        __syncthreads();
        s[threadIdx.x] += t;
        __syncthreads();
    }
    if (i < n) incl[i] = s[threadIdx.x];
    if (threadIdx.x == 255) bsum[blockIdx.x] = s[255];
}
__global__ void scanB(int* __restrict__ bsum, int nb) {
    __shared__ int s[256];
    int v = (threadIdx.x < nb) ? bsum[threadIdx.x] : 0;
    s[threadIdx.x] = v;
    __syncthreads();
#pragma unroll
    for (int off = 1; off < 256; off <<= 1) {
        int t = (threadIdx.x >= off) ? s[threadIdx.x - off] : 0;
        __syncthreads();
        s[threadIdx.x] += t;
        __syncthreads();
    }
    if (threadIdx.x < nb) bsum[threadIdx.x] = s[threadIdx.x] - v;  // exclusive
}
__global__ void scanC(int* __restrict__ rs_incl, const int* __restrict__ cnt,
                      const int* __restrict__ boff, int* __restrict__ cur, int n) {
    int i = blockIdx.x * blockDim.x + threadIdx.x;
    if (i >= n) return;
    int v = rs_incl[i] - cnt[i] + boff[i >> 8];
    rs_incl[i] = v;
    cur[i] = v;
}
__global__ void fill_edges(const int* __restrict__ src, const int* __restrict__ tgt,
                           const int* __restrict__ et, int* __restrict__ cur,
                           int2* __restrict__ eidx, int E) {
    int e = blockIdx.x * blockDim.x + threadIdx.x;
    if (e >= E) return;
    int t = tgt[e];
    int slot = atomicAdd(&cur[t], 1);
    eidx[slot] = make_int2(src[e], et[e]);
}

// ---------------- packed-operand bf16x3 GEMM, cp.async double-buffered ------
// EPI 0: f32 out Cf. EPI 1: packed hi/lo out + bias. EPI 2: rgcn dual
//        (by<8 -> fp16x2 Y; by==8 -> f32 Cagg).
// A smem: [buf][row][kpair] stride 12 (bank-bijective for cp.async + LDS).
// B smem: [buf][kpair][col] stride 136.
template<int EPI>
__global__ __launch_bounds__(256, 2) void gemm_pk(
    const uint32_t* __restrict__ Ahi, const uint32_t* __restrict__ Alo,
    const uint32_t* __restrict__ Bhi_base, const uint32_t* __restrict__ Blo_base,
    const float* __restrict__ bias,
    float* __restrict__ Cf, float* __restrict__ Cagg,
    uint32_t* __restrict__ Chi, uint32_t* __restrict__ Clo,
    int M, int Kw)
{
    __shared__ uint32_t As_h[2][128][12], As_l[2][128][12];
    __shared__ uint32_t Bs_h[2][8][136], Bs_l[2][8][136];

    const int tid = threadIdx.x;
    const int lane = tid & 31;
    const int warp = tid >> 5;
    const int warp_m = warp & 3;
    const int warp_n = warp >> 2;
    const int bm = blockIdx.x * 128;
    const int by = blockIdx.y;

    const uint32_t* Bhi = Bhi_base + (size_t)by * Kw * HH;
    const uint32_t* Blo = Blo_base + (size_t)by * Kw * HH;

    const int a_row = tid & 127;
    const int a_kq = (tid >> 7) << 2;     // 0 or 4
    const int b_kp = tid >> 5;            // 0..7
    const int b_n4 = (tid & 31) << 2;     // 0..124

    const int row_g = bm + a_row;
    const bool row_ok = (row_g < M);
    const int row_c = row_ok ? row_g : 0;

    const uint32_t sAh = (uint32_t)__cvta_generic_to_shared(&As_h[0][0][0]);
    const uint32_t sAl = (uint32_t)__cvta_generic_to_shared(&As_l[0][0][0]);
    const uint32_t sBh = (uint32_t)__cvta_generic_to_shared(&Bs_h[0][0][0]);
    const uint32_t sBl = (uint32_t)__cvta_generic_to_shared(&Bs_l[0][0][0]);

    const uint32_t daOff = (uint32_t)((a_row * 12 + a_kq) * 4);
    const uint32_t dbOff = (uint32_t)((b_kp * 136 + b_n4) * 4);

    const int tig = lane & 3;
    const int gid = lane >> 2;

    float c[2][8][4];
#pragma unroll
    for (int i = 0; i < 2; i++)
#pragma unroll
        for (int j = 0; j < 8; j++)
#pragma unroll
            for (int q = 0; q < 4; q++) c[i][j][q] = 0.0f;

    auto issue = [&](int kp0, int buf) {
        uint32_t da = daOff + (uint32_t)(buf * 128 * 12 * 4);
        cpa16(sAh + da, Ahi + (size_t)row_c * Kw + kp0 + a_kq, row_ok);
        cpa16(sAl + da, Alo + (size_t)row_c * Kw + kp0 + a_kq, row_ok);
        uint32_t db = dbOff + (uint32_t)(buf * 8 * 136 * 4);
        cpa16(sBh + db, Bhi + (size_t)(kp0 + b_kp) * HH + b_n4, true);
        cpa16(sBl + db, Blo + (size_t)(kp0 + b_kp) * HH + b_n4, true);
        asm volatile("cp.async.commit_group;" ::: "memory");
    };

    const int NIT = Kw / 8;
    issue(0, 0);
#pragma unroll 1
    for (int it = 0; it < NIT; it++) {
        const int buf = it & 1;
        if (it + 1 < NIT) {
            issue((it + 1) * 8, buf ^ 1);
            asm volatile("cp.async.wait_group 1;" ::: "memory");
        } else {
            asm volatile("cp.async.wait_group 0;" ::: "memory");
        }
        __syncthreads();

        uint32_t ah[2][4], al[2][4];
#pragma unroll
        for (int mt = 0; mt < 2; mt++) {
            int r = warp_m * 32 + mt * 16 + gid;
            ah[mt][0] = As_h[buf][r][tig];     ah[mt][1] = As_h[buf][r + 8][tig];
            ah[mt][2] = As_h[buf][r][tig + 4]; ah[mt][3] = As_h[buf][r + 8][tig + 4];
            al[mt][0] = As_l[buf][r][tig];     al[mt][1] = As_l[buf][r + 8][tig];
            al[mt][2] = As_l[buf][r][tig + 4]; al[mt][3] = As_l[buf][r + 8][tig + 4];
        }
#pragma unroll
        for (int half = 0; half < 2; half++) {
            uint32_t bh[4][2], bl[4][2];
#pragma unroll
            for (int n4 = 0; n4 < 4; n4++) {
                int cc = warp_n * 64 + (half * 4 + n4) * 8 + gid;
                bh[n4][0] = Bs_h[buf][tig][cc]; bh[n4][1] = Bs_h[buf][tig + 4][cc];
                bl[n4][0] = Bs_l[buf][tig][cc]; bl[n4][1] = Bs_l[buf][tig + 4][cc];
            }
#pragma unroll
            for (int mt = 0; mt < 2; mt++)
#pragma unroll
                for (int n4 = 0; n4 < 4; n4++) {
                    int nt = half * 4 + n4;
                    mma_bf16(c[mt][nt][0], c[mt][nt][1], c[mt][nt][2], c[mt][nt][3],
                             ah[mt][0], ah[mt][1], ah[mt][2], ah[mt][3],
                             bh[n4][0], bh[n4][1]);
                    mma_bf16(c[mt][nt][0], c[mt][nt][1], c[mt][nt][2], c[mt][nt][3],
                             ah[mt][0], ah[mt][1], ah[mt][2], ah[mt][3],
                             bl[n4][0], bl[n4][1]);
                    mma_bf16(c[mt][nt][0], c[mt][nt][1], c[mt][nt][2], c[mt][nt][3],
                             al[mt][0], al[mt][1], al[mt][2], al[mt][3],
                             bh[n4][0], bh[n4][1]);
                }
        }
        __syncthreads();
    }

    const int er0 = bm + warp_m * 32 + gid;
    const int ec0 = warp_n * 64 + (tig << 1);
#pragma unroll
    for (int mt = 0; mt < 2; mt++) {
#pragma unroll
        for (int half = 0; half < 2; half++) {
            int row = er0 + mt * 16 + half * 8;
            if (row >= M) continue;
#pragma unroll
            for (int nt = 0; nt < 8; nt++) {
                int col = ec0 + nt * 8;
                float v0 = c[mt][nt][half * 2 + 0];
                float v1 = c[mt][nt][half * 2 + 1];
                if (EPI == 1 && bias) { v0 += bias[col]; v1 += bias[col + 1]; }
                if (EPI == 0) {
                    *(float2*)(Cf + (size_t)row * HH + col) = make_float2(v0, v1);
                } else if (EPI == 1) {
                    uint32_t hp, lp; split2(v0, v1, hp, lp);
                    Chi[(size_t)row * KW_H + (col >> 1)] = hp;
                    Clo[(size_t)row * KW_H + (col >> 1)] = lp;
                } else {
                    if (by < 8) {
                        __half2 hv = __floats2half2_rn(v0, v1);
                        Chi[(size_t)row * (RR * KW_H) + by * KW_H + (col >> 1)] =
                            *(uint32_t*)&hv;
                    } else {
                        *(float2*)(Cagg + (size_t)row * HH + col) = make_float2(v0, v1);
                    }
                }
            }
        }
    }
}

// ---------------- degree ----------------
__global__ void deg_count(const int* __restrict__ tgt, const int* __restrict__ et,
                          float* __restrict__ deg, int E) {
    int e = blockIdx.x * blockDim.x + threadIdx.x;
    if (e >= E) return;
    atomicAdd(deg + (size_t)tgt[e] * RR + et[e], 1.0f);
}
__global__ void make_invdeg(float* deg, int n) {
    int i = blockIdx.x * blockDim.x + threadIdx.x;
    if (i < n) deg[i] = 1.0f / fmaxf(deg[i], 1.0f);
}

// ---------------- RGCN gather: warp per target node ----------------
__global__ void rgcn_gather(const int2* __restrict__ eidx, const int* __restrict__ rs,
                            const int* __restrict__ cnt, const uint32_t* __restrict__ Yh,
                            const float* __restrict__ invdeg, const float* __restrict__ aggroot,
                            const float* __restrict__ b,
                            uint32_t* __restrict__ dhi, uint32_t* __restrict__ dlo, int n)
{
    int w = (blockIdx.x * blockDim.x + threadIdx.x) >> 5;
    int lane = threadIdx.x & 31;
    if (w >= n) return;
    float4 a0 = ((const float4*)(aggroot + (size_t)w * HH))[lane];
    float acc[4] = { a0.x, a0.y, a0.z, a0.w };
    int s0 = rs[w], e1 = s0 + cnt[w];
#pragma unroll 2
    for (int e = s0; e < e1; e++) {
        int2 p = eidx[e];
        float iv = invdeg[(size_t)w * RR + p.y];
        uint2 pk = ((const uint2*)(Yh + ((size_t)p.x * RR + p.y) * KW_H))[lane];
        float2 f0 = __half22float2(*(__half2*)&pk.x);
        float2 f1 = __half22float2(*(__half2*)&pk.y);
        acc[0] += f0.x * iv; acc[1] += f0.y * iv;
        acc[2] += f1.x * iv; acc[3] += f1.y * iv;
    }
    int col = lane * 4;
    float v0 = fmaxf(acc[0] + b[col + 0], 0.f);
    float v1 = fmaxf(acc[1] + b[col + 1], 0.f);
    float v2 = fmaxf(acc[2] + b[col + 2], 0.f);
    float v3 = fmaxf(acc[3] + b[col + 3], 0.f);
    uint32_t h0, l0, h1, l1;
    split2(v0, v1, h0, l0);
    split2(v2, v3, h1, l1);
    ((uint2*)(dhi + (size_t)w * KW_H))[lane] = make_uint2(h0, h1);
    ((uint2*)(dlo + (size_t)w * KW_H))[lane] = make_uint2(l0, l1);
}

// ---------------- GAT ----------------
__global__ void att_node(const float* __restrict__ z, const float* __restrict__ att,
                         float* __restrict__ asrc, float* __restrict__ atgt, int n)
{
    int i = blockIdx.x * blockDim.x + threadIdx.x;
    if (i >= n * HEADS) return;
    int node = i >> 3, hd = i & 7;
    const float* zp = z + (size_t)node * HH + hd * DHH;
    const float* al = att + hd * (2 * DHH);
    float sa = 0.f, sb = 0.f;
#pragma unroll
    for (int d = 0; d < DHH; d++) {
        float zv = zp[d];
        sa += zv * al[d];
        sb += zv * al[DHH + d];
    }
    asrc[i] = sa;
    atgt[i] = sb;
}

// fused GAT gather + normalize + bg + Wf projection + log_softmax.
__global__ void gat_gather(const int2* __restrict__ eidx, const int* __restrict__ rs,
                           const int* __restrict__ cnt,
                           const float* __restrict__ asrc, const float* __restrict__ atgt,
                           const float* __restrict__ z, const float* __restrict__ bg,
                           const float* __restrict__ Wf, const float* __restrict__ bf,
                           float* __restrict__ out, int n)
{
    int w = (blockIdx.x * blockDim.x + threadIdx.x) >> 5;
    int lane = threadIdx.x & 31;
    if (w >= n) return;
    int head = lane >> 2;
    float at = atgt[(size_t)w * HEADS + head];
    float acc[4] = { 0.f, 0.f, 0.f, 0.f };
    float den = 0.f;
    int s0 = rs[w], e1 = s0 + cnt[w];
#pragma unroll 2
    for (int e = s0; e < e1; e++) {
        int s = eidx[e].x;
        float a = asrc[(size_t)s * HEADS + head] + at;
        a = a > 0.f ? a : 0.2f * a;
        float ex = __expf(a);
        den += ex;
        float4 zv = ((const float4*)(z + (size_t)s * HH))[lane];
        acc[0] += zv.x * ex; acc[1] += zv.y * ex;
        acc[2] += zv.z * ex; acc[3] += zv.w * ex;
    }
    float inv = 1.0f / fmaxf(den, 1e-16f);
    float4 bgv = ((const float4*)bg)[lane];
    float gv[4] = { acc[0] * inv + bgv.x, acc[1] * inv + bgv.y,
                    acc[2] * inv + bgv.z, acc[3] * inv + bgv.w };
    float a0 = 0.f, a1 = 0.f, a2 = 0.f;
    int j0 = lane * 4;
#pragma unroll
    for (int c = 0; c < 4; c++) {
        int j = j0 + c;
        a0 += gv[c] * Wf[j * OUTC + 0];
        a1 += gv[c] * Wf[j * OUTC + 1];
        a2 += gv[c] * Wf[j * OUTC + 2];
    }
#pragma unroll
    for (int off = 16; off > 0; off >>= 1) {
        a0 += __shfl_xor_sync(0xFFFFFFFFu, a0, off);
        a1 += __shfl_xor_sync(0xFFFFFFFFu, a1, off);
        a2 += __shfl_xor_sync(0xFFFFFFFFu, a2, off);
    }
    if (lane == 0) {
        float l0 = a0 + bf[0], l1 = a1 + bf[1], l2 = a2 + bf[2];
        float m = fmaxf(l0, fmaxf(l1, l2));
        float lse = m + logf(expf(l0 - m) + expf(l1 - m) + expf(l2 - m));
        out[(size_t)w * OUTC + 0] = l0 - lse;
        out[(size_t)w * OUTC + 1] = l1 - lse;
        out[(size_t)w * OUTC + 2] = l2 - lse;
    }
}

// ---------------- launch ----------------
extern "C" void kernel_launch(void* const* d_in, const int* in_sizes, int n_in,
                              void* d_out, int out_size)
{
    const float* x     = (const float*)d_in[0];
    const int*   ei    = (const int*)d_in[1];
    const int*   etype = (const int*)d_in[2];
    const float* Wp    = (const float*)d_in[3];
    const float* bp    = (const float*)d_in[4];
    const float* W1    = (const float*)d_in[5];
    const float* root1 = (const float*)d_in[6];
    const float* b1    = (const float*)d_in[7];
    const float* W2    = (const float*)d_in[8];
    const float* root2 = (const float*)d_in[9];
    const float* b2    = (const float*)d_in[10];
    const float* Wg    = (const float*)d_in[11];
    const float* att   = (const float*)d_in[12];
    const float* bg    = (const float*)d_in[13];
    const float* Wf    = (const float*)d_in[14];
    const float* bf    = (const float*)d_in[15];
    float* out = (float*)d_out;

    const int* src = ei;
    const int* tgt = ei + EE;

    float *agg, *z, *deg, *asrc, *atgt;
    uint32_t *Yh;
    uint32_t *xhi, *xlo, *hAhi, *hAlo, *hBhi, *hBlo;
    uint32_t *w1hi, *w1lo, *w2hi, *w2lo, *wphi, *wplo, *wghi, *wglo;
    int *cnt, *rs, *cur, *bsum;
    int2* eidx;
    cudaGetSymbolAddress((void**)&Yh, g_Yh);
    cudaGetSymbolAddress((void**)&agg, g_agg);
    cudaGetSymbolAddress((void**)&z, g_z);
    cudaGetSymbolAddress((void**)&deg, g_deg);
    cudaGetSymbolAddress((void**)&asrc, g_asrc);
    cudaGetSymbolAddress((void**)&atgt, g_atgt);
    cudaGetSymbolAddress((void**)&xhi, g_xhi);
    cudaGetSymbolAddress((void**)&xlo, g_xlo);
    cudaGetSymbolAddress((void**)&hAhi, g_hAhi);
    cudaGetSymbolAddress((void**)&hAlo, g_hAlo);
    cudaGetSymbolAddress((void**)&hBhi, g_hBhi);
    cudaGetSymbolAddress((void**)&hBlo, g_hBlo);
    cudaGetSymbolAddress((void**)&w1hi, g_w1hi);
    cudaGetSymbolAddress((void**)&w1lo, g_w1lo);
    cudaGetSymbolAddress((void**)&w2hi, g_w2hi);
    cudaGetSymbolAddress((void**)&w2lo, g_w2lo);
    cudaGetSymbolAddress((void**)&wphi, g_wphi);
    cudaGetSymbolAddress((void**)&wplo, g_wplo);
    cudaGetSymbolAddress((void**)&wghi, g_wghi);
    cudaGetSymbolAddress((void**)&wglo, g_wglo);
    cudaGetSymbolAddress((void**)&cnt, g_cnt);
    cudaGetSymbolAddress((void**)&rs, g_rs);
    cudaGetSymbolAddress((void**)&cur, g_cur);
    cudaGetSymbolAddress((void**)&bsum, g_bsum);
    cudaGetSymbolAddress((void**)&eidx, g_eidx);

    const int gemmGrid = (NN + 127) / 128;         // 391
    const int nodeGrid = (NN * 32 + 255) / 256;    // warp per node
    const int NB = (NN + 255) / 256;

    // ---- one-time packs / splits / degrees / CSR ----
    {
        dim3 g1((KW_H * HH + 255) / 256, 9);
        pack_b<<<g1, 256>>>(W1, root1, w1hi, w1lo, KW_H);
        pack_b<<<g1, 256>>>(W2, root2, w2hi, w2lo, KW_H);
        dim3 g2((KW_X * HH + 255) / 256, 1);
        pack_b<<<g2, 256>>>(Wp, nullptr, wphi, wplo, KW_X);
        dim3 g3((KW_H * HH + 255) / 256, 1);
        pack_b<<<g3, 256>>>(Wg, nullptr, wghi, wglo, KW_H);
    }
    split_mat<<<(NN * KW_X + 255) / 256, 256>>>(x, xhi, xlo, NN * KW_X);
    fill_f4<<<64, 256>>>((float4*)deg, NN * RR / 4, 0.f);
    deg_count<<<(EE + 255) / 256, 256>>>(tgt, etype, deg, EE);
    make_invdeg<<<(NN * RR + 255) / 256, 256>>>(deg, NN * RR);
    fill_i<<<NB, 256>>>(cnt, NN, 0);
    hist_tgt<<<(EE + 255) / 256, 256>>>(tgt, cnt, EE);
    scanA<<<NB, 256>>>(cnt, rs, bsum, NN);
    scanB<<<1, 256>>>(bsum, NB);
    scanC<<<NB, 256>>>(rs, cnt, bsum, cur, NN);
    fill_edges<<<(EE + 255) / 256, 256>>>(src, tgt, etype, cur, eidx, EE);

    // ---- projection: hA = pack(x @ Wp + bp)
    gemm_pk<1><<<dim3(gemmGrid, 1), 256>>>(xhi, xlo, wphi, wplo, bp,
                                           nullptr, nullptr, hAhi, hAlo, NN, KW_X);

    // ---- RGCN layer 1 ----
    gemm_pk<2><<<dim3(gemmGrid, 9), 256>>>(hAhi, hAlo, w1hi, w1lo, nullptr,
                                           nullptr, agg, Yh, nullptr, NN, KW_H);
    rgcn_gather<<<nodeGrid, 256>>>(eidx, rs, cnt, Yh, deg, agg, b1, hBhi, hBlo, NN);

    // ---- RGCN layer 2 ----
    gemm_pk<2><<<dim3(gemmGrid, 9), 256>>>(hBhi, hBlo, w2hi, w2lo, nullptr,
                                           nullptr, agg, Yh, nullptr, NN, KW_H);
    rgcn_gather<<<nodeGrid, 256>>>(eidx, rs, cnt, Yh, deg, agg, b2, hAhi, hAlo, NN);

    // ---- GAT ----
    gemm_pk<0><<<dim3(gemmGrid, 1), 256>>>(hAhi, hAlo, wghi, wglo, nullptr,
                                           z, nullptr, nullptr, nullptr, NN, KW_H);
    att_node<<<(NN * HEADS + 255) / 256, 256>>>(z, att, asrc, atgt, NN);
    gat_gather<<<nodeGrid, 256>>>(eidx, rs, cnt, asrc, atgt, z, bg, Wf, bf, out, NN);
}